// round 9
// baseline (speedup 1.0000x reference)
#include <cuda_runtime.h>
#include <cuda_bf16.h>
#include <cstdint>

// Problem constants (match reference setup_inputs)
constexpr int B_ = 2;
constexpr int H_ = 16;
constexpr int S_ = 2048;
constexpr int D_ = 1024;     // d_model
constexpr int DK_ = 64;      // head dim
constexpr int M_ = B_ * S_;  // 4096 rows in all GEMMs

// Q pre-scale: 1/sqrt(Dk) * log2(e) so softmax uses exp2 directly
#define QSCALE 0.18033688011112042f
#define NEGB  (-1.0e8f)

// ==================== PTX helpers (sm_80-baseline only) ====================
__device__ __forceinline__ uint32_t smem_to_u32(const void* p) {
    uint32_t a;
    asm("{ .reg .u64 t; cvta.to.shared.u64 t, %1; cvt.u32.u64 %0, t; }" : "=r"(a) : "l"(p));
    return a;
}
__device__ __forceinline__ void cp_async16(uint32_t dst, const void* src) {
    asm volatile("cp.async.cg.shared.global [%0], [%1], 16;" :: "r"(dst), "l"(src));
}
__device__ __forceinline__ void cp_commit() {
    asm volatile("cp.async.commit_group;");
}
template <int N>
__device__ __forceinline__ void cp_wait() {
    asm volatile("cp.async.wait_group %0;" :: "n"(N));
}
__device__ __forceinline__ void ldm_x4(uint32_t& r0, uint32_t& r1, uint32_t& r2, uint32_t& r3,
                                       uint32_t addr) {
    asm volatile("ldmatrix.sync.aligned.m8n8.x4.shared.b16 {%0,%1,%2,%3}, [%4];"
                 : "=r"(r0), "=r"(r1), "=r"(r2), "=r"(r3) : "r"(addr));
}
__device__ __forceinline__ void ldm_x4_t(uint32_t& r0, uint32_t& r1, uint32_t& r2, uint32_t& r3,
                                         uint32_t addr) {
    asm volatile("ldmatrix.sync.aligned.m8n8.x4.trans.shared.b16 {%0,%1,%2,%3}, [%4];"
                 : "=r"(r0), "=r"(r1), "=r"(r2), "=r"(r3) : "r"(addr));
}
__device__ __forceinline__ void mma_bf16(float* c, const uint32_t* a, const uint32_t* b) {
    asm volatile(
        "mma.sync.aligned.m16n8k16.row.col.f32.bf16.bf16.f32 "
        "{%0,%1,%2,%3}, {%4,%5,%6,%7}, {%8,%9}, {%0,%1,%2,%3};"
        : "+f"(c[0]), "+f"(c[1]), "+f"(c[2]), "+f"(c[3])
        : "r"(a[0]), "r"(a[1]), "r"(a[2]), "r"(a[3]), "r"(b[0]), "r"(b[1]));
}
__device__ __forceinline__ float ex2(float x) {
    float y;
    asm("ex2.approx.f32 %0, %1;" : "=f"(y) : "f"(x));
    return y;
}
// split (a,b) fp32 pair into packed bf16x2 hi + lo
__device__ __forceinline__ void split2(float a, float b, uint32_t& hi, uint32_t& lo) {
    __nv_bfloat162 h = __floats2bfloat162_rn(a, b);
    float2 hf = __bfloat1622float2(h);
    __nv_bfloat162 l = __floats2bfloat162_rn(a - hf.x, b - hf.y);
    hi = *(uint32_t*)&h;
    lo = *(uint32_t*)&l;
}

// -------------------- device scratch (no allocations allowed) --------------------
__device__ __nv_bfloat16 g_Qh[(size_t)B_ * H_ * S_ * DK_];
__device__ __nv_bfloat16 g_Ql[(size_t)B_ * H_ * S_ * DK_];
__device__ __nv_bfloat16 g_Kh[(size_t)B_ * H_ * S_ * DK_];
__device__ __nv_bfloat16 g_Kl[(size_t)B_ * H_ * S_ * DK_];
__device__ __nv_bfloat16 g_Vh[(size_t)B_ * H_ * S_ * DK_];
__device__ __nv_bfloat16 g_Vl[(size_t)B_ * H_ * S_ * DK_];
__device__ __nv_bfloat16 g_ctxH[(size_t)M_ * D_];
__device__ __nv_bfloat16 g_ctxL[(size_t)M_ * D_];
__device__ __nv_bfloat16 g_actH[3][(size_t)M_ * D_];
__device__ __nv_bfloat16 g_actL[3][(size_t)M_ * D_];
__device__ __nv_bfloat16 g_wTH[4][(size_t)D_ * D_];
__device__ __nv_bfloat16 g_wTL[4][(size_t)D_ * D_];

// ==================== conversion kernels ====================
__global__ __launch_bounds__(256) void conv_hl_kernel(const float* __restrict__ src, int which) {
    __nv_bfloat16* hi = g_actH[which];
    __nv_bfloat16* lo = g_actL[which];
    int i = blockIdx.x * blockDim.x + threadIdx.x;   // float4 index
    float4 v = ((const float4*)src)[i];
    float f[4] = {v.x, v.y, v.z, v.w};
    __nv_bfloat16 h[4], l[4];
#pragma unroll
    for (int j = 0; j < 4; j++) {
        h[j] = __float2bfloat16(f[j]);
        l[j] = __float2bfloat16(f[j] - __bfloat162float(h[j]));
    }
    ((__nv_bfloat162*)hi)[i * 2 + 0] = __nv_bfloat162(h[0], h[1]);
    ((__nv_bfloat162*)hi)[i * 2 + 1] = __nv_bfloat162(h[2], h[3]);
    ((__nv_bfloat162*)lo)[i * 2 + 0] = __nv_bfloat162(l[0], l[1]);
    ((__nv_bfloat162*)lo)[i * 2 + 1] = __nv_bfloat162(l[2], l[3]);
}

// W [K,N] fp32 -> transposed hi/lo bf16 [N,K]
__global__ __launch_bounds__(256) void conv_wT_kernel(const float* __restrict__ W, int which) {
    __shared__ float t[32][33];
    const int n0 = blockIdx.x * 32, k0 = blockIdx.y * 32;
    const int tx = threadIdx.x, ty = threadIdx.y;     // block (32,8)
#pragma unroll
    for (int r = 0; r < 32; r += 8)
        t[ty + r][tx] = W[(size_t)(k0 + ty + r) * D_ + n0 + tx];
    __syncthreads();
    __nv_bfloat16* hi = g_wTH[which];
    __nv_bfloat16* lo = g_wTL[which];
#pragma unroll
    for (int r = 0; r < 32; r += 8) {
        float v = t[tx][ty + r];
        __nv_bfloat16 h = __float2bfloat16(v);
        __nv_bfloat16 l = __float2bfloat16(v - __bfloat162float(h));
        size_t o = (size_t)(n0 + ty + r) * D_ + k0 + tx;
        hi[o] = h; lo[o] = l;
    }
}

// ==================== mma.sync GEMM (3x bf16 split) ====================
constexpr int BM = 128, BN = 128, BK = 32;
constexpr int TPAD = 40;
constexpr int TILE_B = 128 * TPAD * 2;
constexpr int STAGE_B = 4 * TILE_B;
constexpr int GSMEM = 2 * STAGE_B;
constexpr int NC = D_ / BK;

template <int TGT>
__global__ __launch_bounds__(256, 2) void gemm_mma_kernel(const float* __restrict__ bias,
                                                          float* __restrict__ outp) {
    extern __shared__ __align__(128) char sm[];
    const uint32_t smbase = smem_to_u32(sm);
    const int tid = threadIdx.x, wid = tid >> 5, lane = tid & 31;
    const int m0 = blockIdx.y * BM, n0 = blockIdx.x * BN;
    const int wm = (wid & 3) * 32, wn = (wid >> 2) * 64;

    const __nv_bfloat16* Ah;
    const __nv_bfloat16* Al;
    if constexpr (TGT < 3) { Ah = g_actH[TGT]; Al = g_actL[TGT]; }
    else                   { Ah = g_ctxH;      Al = g_ctxL;      }
    const __nv_bfloat16* Bh = g_wTH[TGT];
    const __nv_bfloat16* Bl = g_wTL[TGT];

    float acc[2][8][4];
#pragma unroll
    for (int i = 0; i < 2; i++)
#pragma unroll
        for (int j = 0; j < 8; j++)
#pragma unroll
            for (int q = 0; q < 4; q++) acc[i][j][q] = 0.f;

    auto issue_load = [&](int c) {
        const int s = c & 1, k0 = c * BK;
        const uint32_t st = smbase + s * STAGE_B;
#pragma unroll
        for (int t = 0; t < 8; t++) {
            int i = tid + t * 256;
            int tile = i >> 9, rem = i & 511, row = rem >> 2, cc = rem & 3;
            const __nv_bfloat16* src;
            if (tile == 0)      src = Ah + (size_t)(m0 + row) * D_ + k0 + cc * 8;
            else if (tile == 1) src = Al + (size_t)(m0 + row) * D_ + k0 + cc * 8;
            else if (tile == 2) src = Bh + (size_t)(n0 + row) * D_ + k0 + cc * 8;
            else                src = Bl + (size_t)(n0 + row) * D_ + k0 + cc * 8;
            cp_async16(st + tile * TILE_B + (row * TPAD + cc * 8) * 2, src);
        }
        cp_commit();
    };

    issue_load(0);

    for (int c = 0; c < NC; c++) {
        if (c + 1 < NC) { issue_load(c + 1); cp_wait<1>(); }
        else            { cp_wait<0>(); }
        __syncthreads();

        const uint32_t st = smbase + (c & 1) * STAGE_B;
#pragma unroll
        for (int k16 = 0; k16 < BK; k16 += 16) {
            uint32_t a_hi[2][4], a_lo[2][4];
            const int arow = wm + (lane & 15);
            const int acol = k16 + (lane >> 4) * 8;
#pragma unroll
            for (int i = 0; i < 2; i++) {
                uint32_t off = ((arow + i * 16) * TPAD + acol) * 2;
                ldm_x4(a_hi[i][0], a_hi[i][1], a_hi[i][2], a_hi[i][3], st + off);
                ldm_x4(a_lo[i][0], a_lo[i][1], a_lo[i][2], a_lo[i][3], st + TILE_B + off);
            }
            const int brow_base = wn + ((lane >> 4) & 1) * 8 + (lane & 7);
            const int bcol = k16 + ((lane >> 3) & 1) * 8;
#pragma unroll
            for (int jj = 0; jj < 4; jj++) {
                uint32_t off = ((brow_base + jj * 16) * TPAD + bcol) * 2;
                uint32_t bh[4], bl[4];
                ldm_x4(bh[0], bh[1], bh[2], bh[3], st + 2 * TILE_B + off);
                ldm_x4(bl[0], bl[1], bl[2], bl[3], st + 3 * TILE_B + off);
#pragma unroll
                for (int i = 0; i < 2; i++) {
                    mma_bf16(acc[i][2 * jj + 0], a_hi[i], bh + 0);
                    mma_bf16(acc[i][2 * jj + 0], a_lo[i], bh + 0);
                    mma_bf16(acc[i][2 * jj + 0], a_hi[i], bl + 0);
                    mma_bf16(acc[i][2 * jj + 1], a_hi[i], bh + 2);
                    mma_bf16(acc[i][2 * jj + 1], a_lo[i], bh + 2);
                    mma_bf16(acc[i][2 * jj + 1], a_hi[i], bl + 2);
                }
            }
        }
        __syncthreads();
    }

    // ---- epilogue ----
    const int tr = lane >> 2, tc = (lane & 3) * 2;
#pragma unroll
    for (int i = 0; i < 2; i++) {
#pragma unroll
        for (int hh = 0; hh < 2; hh++) {
            const int m = m0 + wm + i * 16 + tr + hh * 8;
            if constexpr (TGT < 3) {
                __nv_bfloat16* Hdst;
                __nv_bfloat16* Ldst;
                if constexpr (TGT == 0)      { Hdst = g_Qh; Ldst = g_Ql; }
                else if constexpr (TGT == 1) { Hdst = g_Kh; Ldst = g_Kl; }
                else                         { Hdst = g_Vh; Ldst = g_Vl; }
                const int hd = (n0 + wn) >> 6;
                const int b = m >> 11, sq = m & (S_ - 1);
                const size_t rowbase = ((size_t)((b * H_ + hd) * S_ + sq)) * DK_;
#pragma unroll
                for (int j = 0; j < 8; j++) {
                    const int n = n0 + wn + j * 8 + tc;
                    float vx = acc[i][j][hh * 2 + 0] + bias[n];
                    float vy = acc[i][j][hh * 2 + 1] + bias[n + 1];
                    if constexpr (TGT == 0) { vx *= QSCALE; vy *= QSCALE; }
                    uint32_t phi, plo;
                    split2(vx, vy, phi, plo);
                    *(uint32_t*)&Hdst[rowbase + j * 8 + tc] = phi;
                    *(uint32_t*)&Ldst[rowbase + j * 8 + tc] = plo;
                }
            } else {
                float* p = outp + (size_t)m * D_ + n0 + wn + tc;
#pragma unroll
                for (int j = 0; j < 8; j++) {
                    const int n = n0 + wn + j * 8 + tc;
                    float2 o;
                    o.x = acc[i][j][hh * 2 + 0] + bias[n];
                    o.y = acc[i][j][hh * 2 + 1] + bias[n + 1];
                    *(float2*)(p + j * 8) = o;
                }
            }
        }
    }
}

// ==================== mma.sync flash attention ====================
// CTA: 128 q-rows, 8 warps (16 q-rows each), key tile = 64 -> 108 KB smem
// so 2 CTAs/SM co-reside (softmax of one CTA overlaps mma of the other).
constexpr int KT = 64;                            // keys per tile
constexpr int KPAD = 72;                          // padded row (bf16)
constexpr int QTILE = 128 * KPAD * 2;             // 18432 B  (Q operand tile, 128 rows)
constexpr int ATILE = KT * KPAD * 2;              // 9216 B   (K/V tile, 64 rows)
constexpr int ASTAGE = 4 * ATILE;                 // Khi,Klo,Vhi,Vlo = 36864 B
constexpr int AQBYTES = 2 * QTILE;                // Qhi,Qlo = 36864 B
constexpr int ASMEM = AQBYTES + 2 * ASTAGE;       // 110592 B

__global__ __launch_bounds__(256, 2) void attn_mma_kernel(const int* __restrict__ mask) {
    extern __shared__ __align__(128) char smem_raw[];
    const uint32_t smbase = smem_to_u32(smem_raw);
    const int tid = threadIdx.x, wid = tid >> 5, lane = tid & 31;
    const int bh = blockIdx.y, b = bh >> 4, h = bh & 15;
    const int q0 = blockIdx.x * 128;

    const size_t hb = (size_t)bh * S_ * DK_;
    const __nv_bfloat16* Qhg = g_Qh + hb;
    const __nv_bfloat16* Qlg = g_Ql + hb;
    const __nv_bfloat16* Khg = g_Kh + hb;
    const __nv_bfloat16* Klg = g_Kl + hb;
    const __nv_bfloat16* Vhg = g_Vh + hb;
    const __nv_bfloat16* Vlg = g_Vl + hb;

    // ---- issue Q tile loads (hi/lo): 2048 x 16B chunks ----
#pragma unroll
    for (int it = 0; it < 8; it++) {
        int flat = tid + it * 256;
        int tile = flat >> 10, rem = flat & 1023;
        int row = rem >> 3, c8 = rem & 7;
        const __nv_bfloat16* src = (tile == 0 ? Qhg : Qlg) + (size_t)(q0 + row) * DK_ + c8 * 8;
        cp_async16(smbase + tile * QTILE + row * (KPAD * 2) + c8 * 16, src);
    }
    cp_commit();

    auto issue_stage = [&](int t) {
        const int k0t = t * KT;
        const uint32_t st = smbase + AQBYTES + (t & 1) * ASTAGE;
#pragma unroll
        for (int it = 0; it < 8; it++) {            // 2048 x 16B chunks
            int flat = tid + it * 256;
            int tile = flat >> 9, rem = flat & 511;
            int row = rem >> 3, c8 = rem & 7;
            const __nv_bfloat16* src;
            if (tile == 0)      src = Khg + (size_t)(k0t + row) * DK_ + c8 * 8;
            else if (tile == 1) src = Klg + (size_t)(k0t + row) * DK_ + c8 * 8;
            else if (tile == 2) src = Vhg + (size_t)(k0t + row) * DK_ + c8 * 8;
            else                src = Vlg + (size_t)(k0t + row) * DK_ + c8 * 8;
            cp_async16(st + tile * ATILE + row * (KPAD * 2) + c8 * 16, src);
        }
        cp_commit();
    };

    issue_stage(0);

    uint32_t qh[4][4], ql[4][4];     // Q A-frags
    float o[8][4];                   // O accumulator: 8 d-ntiles x 4
#pragma unroll
    for (int i = 0; i < 8; i++)
#pragma unroll
        for (int j = 0; j < 4; j++) o[i][j] = 0.f;
    float m0 = -1e30f, m1 = -1e30f, l0 = 0.f, l1 = 0.f;

    const int tr = lane >> 2, tc2 = (lane & 3) * 2;

#pragma unroll 1
    for (int t = 0; t < S_ / KT; t++) {
        if (t + 1 < S_ / KT) { issue_stage(t + 1); cp_wait<1>(); }
        else                 { cp_wait<0>(); }
        __syncthreads();

        if (t == 0) {
            const int arow = wid * 16 + (lane & 15);
            const int acol = (lane >> 4) * 8;
#pragma unroll
            for (int kt = 0; kt < 4; kt++) {
                uint32_t off = (arow * KPAD + kt * 16 + acol) * 2;
                ldm_x4(qh[kt][0], qh[kt][1], qh[kt][2], qh[kt][3], smbase + off);
                ldm_x4(ql[kt][0], ql[kt][1], ql[kt][2], ql[kt][3], smbase + QTILE + off);
            }
        }

        const uint32_t kb = smbase + AQBYTES + (t & 1) * ASTAGE;

        // ---- QK^T: scores [16 q x 64 k] per warp ----
        float sc[8][4];
#pragma unroll
        for (int i = 0; i < 8; i++)
#pragma unroll
            for (int j = 0; j < 4; j++) sc[i][j] = 0.f;

#pragma unroll
        for (int kt = 0; kt < 4; kt++) {
            const int brow = ((lane >> 4) & 1) * 8 + (lane & 7);
            const int bcol = kt * 16 + ((lane >> 3) & 1) * 8;
#pragma unroll
            for (int g = 0; g < 4; g++) {
                uint32_t off = ((g * 16 + brow) * KPAD + bcol) * 2;
                uint32_t bhv[4], blv[4];
                ldm_x4(bhv[0], bhv[1], bhv[2], bhv[3], kb + off);
                ldm_x4(blv[0], blv[1], blv[2], blv[3], kb + ATILE + off);
                mma_bf16(sc[2 * g + 0], qh[kt], bhv + 0);
                mma_bf16(sc[2 * g + 0], ql[kt], bhv + 0);
                mma_bf16(sc[2 * g + 0], qh[kt], blv + 0);
                mma_bf16(sc[2 * g + 1], qh[kt], bhv + 2);
                mma_bf16(sc[2 * g + 1], ql[kt], bhv + 2);
                mma_bf16(sc[2 * g + 1], qh[kt], blv + 2);
            }
        }

        // ---- mask + online softmax ----
        const int2* mrow2 = (const int2*)(mask + b * S_ + t * KT);
        float mx0 = -3.4e38f, mx1 = -3.4e38f;
#pragma unroll
        for (int nt = 0; nt < 8; nt++) {
            int2 mv = mrow2[nt * 4 + (lane & 3)];
            if (mv.x == 0) { sc[nt][0] += NEGB; sc[nt][2] += NEGB; }
            if (mv.y == 0) { sc[nt][1] += NEGB; sc[nt][3] += NEGB; }
            mx0 = fmaxf(mx0, fmaxf(sc[nt][0], sc[nt][1]));
            mx1 = fmaxf(mx1, fmaxf(sc[nt][2], sc[nt][3]));
        }
        mx0 = fmaxf(mx0, __shfl_xor_sync(0xffffffffu, mx0, 1));
        mx0 = fmaxf(mx0, __shfl_xor_sync(0xffffffffu, mx0, 2));
        mx1 = fmaxf(mx1, __shfl_xor_sync(0xffffffffu, mx1, 1));
        mx1 = fmaxf(mx1, __shfl_xor_sync(0xffffffffu, mx1, 2));

        float m0n = fmaxf(m0, mx0), m1n = fmaxf(m1, mx1);
        float c0 = ex2(m0 - m0n), c1 = ex2(m1 - m1n);
        m0 = m0n; m1 = m1n;

        float sum0 = 0.f, sum1 = 0.f;
#pragma unroll
        for (int nt = 0; nt < 8; nt++) {
            sc[nt][0] = ex2(sc[nt][0] - m0n);
            sc[nt][1] = ex2(sc[nt][1] - m0n);
            sc[nt][2] = ex2(sc[nt][2] - m1n);
            sc[nt][3] = ex2(sc[nt][3] - m1n);
            sum0 += sc[nt][0] + sc[nt][1];
            sum1 += sc[nt][2] + sc[nt][3];
        }
        sum0 += __shfl_xor_sync(0xffffffffu, sum0, 1);
        sum0 += __shfl_xor_sync(0xffffffffu, sum0, 2);
        sum1 += __shfl_xor_sync(0xffffffffu, sum1, 1);
        sum1 += __shfl_xor_sync(0xffffffffu, sum1, 2);
        l0 = l0 * c0 + sum0;
        l1 = l1 * c1 + sum1;

        // rescale O
#pragma unroll
        for (int i = 0; i < 8; i++) {
            o[i][0] *= c0; o[i][1] *= c0;
            o[i][2] *= c1; o[i][3] *= c1;
        }

        // ---- P @ V (split P, split V via ldmatrix.trans) ----
#pragma unroll
        for (int kk = 0; kk < 4; kk++) {
            uint32_t ph[4], pl[4];
            split2(sc[2 * kk + 0][0], sc[2 * kk + 0][1], ph[0], pl[0]);
            split2(sc[2 * kk + 0][2], sc[2 * kk + 0][3], ph[1], pl[1]);
            split2(sc[2 * kk + 1][0], sc[2 * kk + 1][1], ph[2], pl[2]);
            split2(sc[2 * kk + 1][2], sc[2 * kk + 1][3], ph[3], pl[3]);

            const int krow = kk * 16 + ((lane >> 3) & 1) * 8 + (lane & 7);
            const int dcol = ((lane >> 4) & 1) * 8;
#pragma unroll
            for (int g = 0; g < 4; g++) {
                uint32_t off = (krow * KPAD + g * 16 + dcol) * 2;
                uint32_t bhv[4], blv[4];
                ldm_x4_t(bhv[0], bhv[1], bhv[2], bhv[3], kb + 2 * ATILE + off);
                ldm_x4_t(blv[0], blv[1], blv[2], blv[3], kb + 3 * ATILE + off);
                mma_bf16(o[2 * g + 0], ph, bhv + 0);
                mma_bf16(o[2 * g + 0], pl, bhv + 0);
                mma_bf16(o[2 * g + 0], ph, blv + 0);
                mma_bf16(o[2 * g + 1], ph, bhv + 2);
                mma_bf16(o[2 * g + 1], pl, bhv + 2);
                mma_bf16(o[2 * g + 1], ph, blv + 2);
            }
        }
        __syncthreads();
    }

    // ---- epilogue: O / l -> bf16 hi/lo ctx ----
    const float inv0 = 1.f / l0, inv1 = 1.f / l1;
    const int r0 = q0 + wid * 16 + tr;
    const size_t base0 = ((size_t)(b * S_ + r0)) * D_ + h * DK_;
    const size_t base1 = ((size_t)(b * S_ + r0 + 8)) * D_ + h * DK_;
#pragma unroll
    for (int nt = 0; nt < 8; nt++) {
        const int d0 = nt * 8 + tc2;
        uint32_t phi, plo;
        split2(o[nt][0] * inv0, o[nt][1] * inv0, phi, plo);
        *(uint32_t*)&g_ctxH[base0 + d0] = phi;
        *(uint32_t*)&g_ctxL[base0 + d0] = plo;
        split2(o[nt][2] * inv1, o[nt][3] * inv1, phi, plo);
        *(uint32_t*)&g_ctxH[base1 + d0] = phi;
        *(uint32_t*)&g_ctxL[base1 + d0] = plo;
    }
}

// ==================== launch ====================
extern "C" void kernel_launch(void* const* d_in, const int* in_sizes, int n_in,
                              void* d_out, int out_size) {
    const float* query = (const float*)d_in[0];
    const float* key   = (const float*)d_in[1];
    const float* value = (const float*)d_in[2];
    const int*   mask  = (const int*)d_in[3];
    const float* Wq = (const float*)d_in[4];
    const float* bq = (const float*)d_in[5];
    const float* Wk = (const float*)d_in[6];
    const float* bk = (const float*)d_in[7];
    const float* Wv = (const float*)d_in[8];
    const float* bv = (const float*)d_in[9];
    const float* Wo = (const float*)d_in[10];
    const float* bo = (const float*)d_in[11];
    float* out = (float*)d_out;

    cudaFuncSetAttribute(gemm_mma_kernel<0>, cudaFuncAttributeMaxDynamicSharedMemorySize, GSMEM);
    cudaFuncSetAttribute(gemm_mma_kernel<1>, cudaFuncAttributeMaxDynamicSharedMemorySize, GSMEM);
    cudaFuncSetAttribute(gemm_mma_kernel<2>, cudaFuncAttributeMaxDynamicSharedMemorySize, GSMEM);
    cudaFuncSetAttribute(gemm_mma_kernel<3>, cudaFuncAttributeMaxDynamicSharedMemorySize, GSMEM);
    cudaFuncSetAttribute(attn_mma_kernel, cudaFuncAttributeMaxDynamicSharedMemorySize, ASMEM);

    // weight transpose + bf16 split
    dim3 wtg(D_ / 32, D_ / 32), wtb(32, 8);
    conv_wT_kernel<<<wtg, wtb>>>(Wq, 0);
    conv_wT_kernel<<<wtg, wtb>>>(Wk, 1);
    conv_wT_kernel<<<wtg, wtb>>>(Wv, 2);
    conv_wT_kernel<<<wtg, wtb>>>(Wo, 3);

    // activation bf16 split
    const int nblk = (M_ * D_ / 4) / 256;    // 4096
    conv_hl_kernel<<<nblk, 256>>>(query, 0);
    conv_hl_kernel<<<nblk, 256>>>(key, 1);
    conv_hl_kernel<<<nblk, 256>>>(value, 2);

    // Q/K/V projections -> bf16 hi/lo head-split
    dim3 gg(D_ / BN, M_ / BM);               // (8, 32)
    gemm_mma_kernel<0><<<gg, 256, GSMEM>>>(bq, nullptr);
    gemm_mma_kernel<1><<<gg, 256, GSMEM>>>(bk, nullptr);
    gemm_mma_kernel<2><<<gg, 256, GSMEM>>>(bv, nullptr);

    // flash attention on tensor cores (2 CTAs/SM)
    dim3 ga(S_ / 128, B_ * H_);              // (16, 32)
    attn_mma_kernel<<<ga, 256, ASMEM>>>(mask);

    // output projection (reads ctx hi/lo written by attention)
    gemm_mma_kernel<3><<<gg, 256, GSMEM>>>(bo, out);
}

// round 12
// speedup vs baseline: 1.1955x; 1.1955x over previous
#include <cuda_runtime.h>
#include <cuda_fp16.h>
#include <cstdint>

// Problem constants (match reference setup_inputs)
constexpr int B_ = 2;
constexpr int H_ = 16;
constexpr int S_ = 2048;
constexpr int D_ = 1024;     // d_model
constexpr int DK_ = 64;      // head dim
constexpr int M_ = B_ * S_;  // 4096 rows in all GEMMs

// Q pre-scale: 1/sqrt(Dk) * log2(e) so softmax uses exp2 directly
#define QSCALE 0.18033688011112042f
#define NEGB  (-1.0e8f)

// ==================== PTX helpers (sm_80-baseline only) ====================
__device__ __forceinline__ uint32_t smem_to_u32(const void* p) {
    uint32_t a;
    asm("{ .reg .u64 t; cvta.to.shared.u64 t, %1; cvt.u32.u64 %0, t; }" : "=r"(a) : "l"(p));
    return a;
}
__device__ __forceinline__ void cp_async16(uint32_t dst, const void* src) {
    asm volatile("cp.async.cg.shared.global [%0], [%1], 16;" :: "r"(dst), "l"(src));
}
__device__ __forceinline__ void cp_commit() {
    asm volatile("cp.async.commit_group;");
}
template <int N>
__device__ __forceinline__ void cp_wait() {
    asm volatile("cp.async.wait_group %0;" :: "n"(N));
}
__device__ __forceinline__ void ldm_x4(uint32_t& r0, uint32_t& r1, uint32_t& r2, uint32_t& r3,
                                       uint32_t addr) {
    asm volatile("ldmatrix.sync.aligned.m8n8.x4.shared.b16 {%0,%1,%2,%3}, [%4];"
                 : "=r"(r0), "=r"(r1), "=r"(r2), "=r"(r3) : "r"(addr));
}
__device__ __forceinline__ void ldm_x4_t(uint32_t& r0, uint32_t& r1, uint32_t& r2, uint32_t& r3,
                                         uint32_t addr) {
    asm volatile("ldmatrix.sync.aligned.m8n8.x4.trans.shared.b16 {%0,%1,%2,%3}, [%4];"
                 : "=r"(r0), "=r"(r1), "=r"(r2), "=r"(r3) : "r"(addr));
}
__device__ __forceinline__ void mma_f16(float* c, const uint32_t* a, const uint32_t* b) {
    asm volatile(
        "mma.sync.aligned.m16n8k16.row.col.f32.f16.f16.f32 "
        "{%0,%1,%2,%3}, {%4,%5,%6,%7}, {%8,%9}, {%0,%1,%2,%3};"
        : "+f"(c[0]), "+f"(c[1]), "+f"(c[2]), "+f"(c[3])
        : "r"(a[0]), "r"(a[1]), "r"(a[2]), "r"(a[3]), "r"(b[0]), "r"(b[1]));
}
__device__ __forceinline__ float ex2(float x) {
    float y;
    asm("ex2.approx.f32 %0, %1;" : "=f"(y) : "f"(x));
    return y;
}
// split (a,b) fp32 pair into packed fp16x2 hi + lo
__device__ __forceinline__ void split2(float a, float b, uint32_t& hi, uint32_t& lo) {
    __half2 h = __floats2half2_rn(a, b);
    float2 hf = __half22float2(h);
    __half2 l = __floats2half2_rn(a - hf.x, b - hf.y);
    hi = *(uint32_t*)&h;
    lo = *(uint32_t*)&l;
}

// -------------------- device scratch (no allocations allowed) --------------------
__device__ __half g_Qh[(size_t)B_ * H_ * S_ * DK_];   // Q hi (pre-scaled)
__device__ __half g_Ql[(size_t)B_ * H_ * S_ * DK_];   // Q lo
__device__ __half g_K1[(size_t)B_ * H_ * S_ * DK_];   // K single fp16
__device__ __half g_V1[(size_t)B_ * H_ * S_ * DK_];   // V single fp16
__device__ __half g_ctxH[(size_t)M_ * D_];
__device__ __half g_ctxL[(size_t)M_ * D_];
__device__ __half g_actH[3][(size_t)M_ * D_];
__device__ __half g_actL[3][(size_t)M_ * D_];
__device__ __half g_wTH[4][(size_t)D_ * D_];
__device__ __half g_wTL[4][(size_t)D_ * D_];

// ==================== conversion kernels (z-merged) ====================
__global__ __launch_bounds__(256) void conv_hl_kernel(const float* __restrict__ q,
                                                      const float* __restrict__ k,
                                                      const float* __restrict__ v) {
    const int which = blockIdx.z;
    const float* src = (which == 0) ? q : (which == 1) ? k : v;
    __half* hi = g_actH[which];
    __half* lo = g_actL[which];
    int i = blockIdx.x * blockDim.x + threadIdx.x;   // float4 index
    float4 val = ((const float4*)src)[i];
    float f[4] = {val.x, val.y, val.z, val.w};
    uint32_t h0, l0, h1, l1;
    split2(f[0], f[1], h0, l0);
    split2(f[2], f[3], h1, l1);
    ((uint32_t*)hi)[i * 2 + 0] = h0;
    ((uint32_t*)hi)[i * 2 + 1] = h1;
    ((uint32_t*)lo)[i * 2 + 0] = l0;
    ((uint32_t*)lo)[i * 2 + 1] = l1;
}

// W [K,N] fp32 -> transposed hi/lo fp16 [N,K]; z selects which of 4 weights
__global__ __launch_bounds__(256) void conv_wT_kernel(const float* __restrict__ Wq,
                                                      const float* __restrict__ Wk,
                                                      const float* __restrict__ Wv,
                                                      const float* __restrict__ Wo) {
    __shared__ float t[32][33];
    const int which = blockIdx.z;
    const float* W = (which == 0) ? Wq : (which == 1) ? Wk : (which == 2) ? Wv : Wo;
    const int n0 = blockIdx.x * 32, k0 = blockIdx.y * 32;
    const int tx = threadIdx.x, ty = threadIdx.y;     // block (32,8)
#pragma unroll
    for (int r = 0; r < 32; r += 8)
        t[ty + r][tx] = W[(size_t)(k0 + ty + r) * D_ + n0 + tx];
    __syncthreads();
    __half* hi = g_wTH[which];
    __half* lo = g_wTL[which];
#pragma unroll
    for (int r = 0; r < 32; r += 8) {
        float v = t[tx][ty + r];
        __half h = __float2half_rn(v);
        __half l = __float2half_rn(v - __half2float(h));
        size_t o = (size_t)(n0 + ty + r) * D_ + k0 + tx;
        hi[o] = h; lo[o] = l;
    }
}

// ==================== mma.sync GEMM mainloop (3x fp16 split) ====================
constexpr int BM = 128, BN = 128, BK = 32;
constexpr int TPAD = 40;
constexpr int TILE_B = 128 * TPAD * 2;
constexpr int STAGE_B = 4 * TILE_B;
constexpr int GSMEM = 2 * STAGE_B;
constexpr int NC = D_ / BK;

__device__ __forceinline__ void gemm_mainloop(float (&acc)[2][8][4],
                                              const __half* __restrict__ Ah,
                                              const __half* __restrict__ Al,
                                              const __half* __restrict__ Bh,
                                              const __half* __restrict__ Bl,
                                              int m0, int n0, uint32_t smbase,
                                              int tid, int lane, int wm, int wn) {
    auto issue_load = [&](int c) {
        const int s = c & 1, k0 = c * BK;
        const uint32_t st = smbase + s * STAGE_B;
#pragma unroll
        for (int t = 0; t < 8; t++) {
            int i = tid + t * 256;
            int tile = i >> 9, rem = i & 511, row = rem >> 2, cc = rem & 3;
            const __half* src;
            if (tile == 0)      src = Ah + (size_t)(m0 + row) * D_ + k0 + cc * 8;
            else if (tile == 1) src = Al + (size_t)(m0 + row) * D_ + k0 + cc * 8;
            else if (tile == 2) src = Bh + (size_t)(n0 + row) * D_ + k0 + cc * 8;
            else                src = Bl + (size_t)(n0 + row) * D_ + k0 + cc * 8;
            cp_async16(st + tile * TILE_B + (row * TPAD + cc * 8) * 2, src);
        }
        cp_commit();
    };

    issue_load(0);

    for (int c = 0; c < NC; c++) {
        if (c + 1 < NC) { issue_load(c + 1); cp_wait<1>(); }
        else            { cp_wait<0>(); }
        __syncthreads();

        const uint32_t st = smbase + (c & 1) * STAGE_B;
#pragma unroll
        for (int k16 = 0; k16 < BK; k16 += 16) {
            uint32_t a_hi[2][4], a_lo[2][4];
            const int arow = wm + (lane & 15);
            const int acol = k16 + (lane >> 4) * 8;
#pragma unroll
            for (int i = 0; i < 2; i++) {
                uint32_t off = ((arow + i * 16) * TPAD + acol) * 2;
                ldm_x4(a_hi[i][0], a_hi[i][1], a_hi[i][2], a_hi[i][3], st + off);
                ldm_x4(a_lo[i][0], a_lo[i][1], a_lo[i][2], a_lo[i][3], st + TILE_B + off);
            }
            const int brow_base = wn + ((lane >> 4) & 1) * 8 + (lane & 7);
            const int bcol = k16 + ((lane >> 3) & 1) * 8;
#pragma unroll
            for (int jj = 0; jj < 4; jj++) {
                uint32_t off = ((brow_base + jj * 16) * TPAD + bcol) * 2;
                uint32_t bh[4], bl[4];
                ldm_x4(bh[0], bh[1], bh[2], bh[3], st + 2 * TILE_B + off);
                ldm_x4(bl[0], bl[1], bl[2], bl[3], st + 3 * TILE_B + off);
#pragma unroll
                for (int i = 0; i < 2; i++) {
                    mma_f16(acc[i][2 * jj + 0], a_hi[i], bh + 0);
                    mma_f16(acc[i][2 * jj + 0], a_lo[i], bh + 0);
                    mma_f16(acc[i][2 * jj + 0], a_hi[i], bl + 0);
                    mma_f16(acc[i][2 * jj + 1], a_hi[i], bh + 2);
                    mma_f16(acc[i][2 * jj + 1], a_lo[i], bh + 2);
                    mma_f16(acc[i][2 * jj + 1], a_hi[i], bl + 2);
                }
            }
        }
        __syncthreads();
    }
}

// QKV projections merged: blockIdx.z selects target (0=Q hi/lo scaled, 1=K, 2=V single fp16)
__global__ __launch_bounds__(256, 2) void gemm_qkv_kernel(const float* __restrict__ bq,
                                                          const float* __restrict__ bk,
                                                          const float* __restrict__ bv) {
    extern __shared__ __align__(128) char sm[];
    const uint32_t smbase = smem_to_u32(sm);
    const int tid = threadIdx.x, wid = tid >> 5, lane = tid & 31;
    const int m0 = blockIdx.y * BM, n0 = blockIdx.x * BN;
    const int wm = (wid & 3) * 32, wn = (wid >> 2) * 64;
    const int tgt = blockIdx.z;
    const float* bias = (tgt == 0) ? bq : (tgt == 1) ? bk : bv;

    float acc[2][8][4];
#pragma unroll
    for (int i = 0; i < 2; i++)
#pragma unroll
        for (int j = 0; j < 8; j++)
#pragma unroll
            for (int q = 0; q < 4; q++) acc[i][j][q] = 0.f;

    gemm_mainloop(acc, g_actH[tgt], g_actL[tgt], g_wTH[tgt], g_wTL[tgt],
                  m0, n0, smbase, tid, lane, wm, wn);

    const int tr = lane >> 2, tc = (lane & 3) * 2;
    const int hd = (n0 + wn) >> 6;
#pragma unroll
    for (int i = 0; i < 2; i++) {
#pragma unroll
        for (int hh = 0; hh < 2; hh++) {
            const int m = m0 + wm + i * 16 + tr + hh * 8;
            const int b = m >> 11, sq = m & (S_ - 1);
            const size_t rowbase = ((size_t)((b * H_ + hd) * S_ + sq)) * DK_;
            if (tgt == 0) {
#pragma unroll
                for (int j = 0; j < 8; j++) {
                    const int n = n0 + wn + j * 8 + tc;
                    float vx = (acc[i][j][hh * 2 + 0] + bias[n]) * QSCALE;
                    float vy = (acc[i][j][hh * 2 + 1] + bias[n + 1]) * QSCALE;
                    uint32_t phi, plo;
                    split2(vx, vy, phi, plo);
                    *(uint32_t*)&g_Qh[rowbase + j * 8 + tc] = phi;
                    *(uint32_t*)&g_Ql[rowbase + j * 8 + tc] = plo;
                }
            } else {
                __half* dst = (tgt == 1) ? g_K1 : g_V1;
#pragma unroll
                for (int j = 0; j < 8; j++) {
                    const int n = n0 + wn + j * 8 + tc;
                    __half2 hv = __floats2half2_rn(acc[i][j][hh * 2 + 0] + bias[n],
                                                   acc[i][j][hh * 2 + 1] + bias[n + 1]);
                    *(__half2*)&dst[rowbase + j * 8 + tc] = hv;
                }
            }
        }
    }
}

// Output projection: reads ctx hi/lo, writes fp32
__global__ __launch_bounds__(256, 2) void gemm_out_kernel(const float* __restrict__ bias,
                                                          float* __restrict__ outp) {
    extern __shared__ __align__(128) char sm[];
    const uint32_t smbase = smem_to_u32(sm);
    const int tid = threadIdx.x, wid = tid >> 5, lane = tid & 31;
    const int m0 = blockIdx.y * BM, n0 = blockIdx.x * BN;
    const int wm = (wid & 3) * 32, wn = (wid >> 2) * 64;

    float acc[2][8][4];
#pragma unroll
    for (int i = 0; i < 2; i++)
#pragma unroll
        for (int j = 0; j < 8; j++)
#pragma unroll
            for (int q = 0; q < 4; q++) acc[i][j][q] = 0.f;

    gemm_mainloop(acc, g_ctxH, g_ctxL, g_wTH[3], g_wTL[3],
                  m0, n0, smbase, tid, lane, wm, wn);

    const int tr = lane >> 2, tc = (lane & 3) * 2;
#pragma unroll
    for (int i = 0; i < 2; i++) {
#pragma unroll
        for (int hh = 0; hh < 2; hh++) {
            const int m = m0 + wm + i * 16 + tr + hh * 8;
            float* p = outp + (size_t)m * D_ + n0 + wn + tc;
#pragma unroll
            for (int j = 0; j < 8; j++) {
                const int n = n0 + wn + j * 8 + tc;
                float2 o;
                o.x = acc[i][j][hh * 2 + 0] + bias[n];
                o.y = acc[i][j][hh * 2 + 1] + bias[n + 1];
                *(float2*)(p + j * 8) = o;
            }
        }
    }
}

// ==================== mma.sync flash attention (fp16, 2-term) ====================
// CTA: 128 q-rows, 8 warps (16 q-rows each), key tile 64.
// Q hi/lo split; K, V single fp16 (quantization = dropped lo term, ~2^-11).
constexpr int KT = 64;
constexpr int KPAD = 72;                          // padded row (halves), 144 B
constexpr int QTILE = 128 * KPAD * 2;             // 18432 B
constexpr int ATILE = KT * KPAD * 2;              // 9216 B
constexpr int ASTAGE = 2 * ATILE;                 // K, V = 18432 B
constexpr int AQBYTES = 2 * QTILE;                // Qhi, Qlo = 36864 B
constexpr int ASMEM = AQBYTES + 2 * ASTAGE;       // 73728 B -> 2 CTAs/SM

__global__ __launch_bounds__(256, 2) void attn_mma_kernel(const int* __restrict__ mask) {
    extern __shared__ __align__(128) char smem_raw[];
    const uint32_t smbase = smem_to_u32(smem_raw);
    const int tid = threadIdx.x, wid = tid >> 5, lane = tid & 31;
    const int bh = blockIdx.y, b = bh >> 4, h = bh & 15;
    const int q0 = blockIdx.x * 128;

    const size_t hb = (size_t)bh * S_ * DK_;
    const __half* Qhg = g_Qh + hb;
    const __half* Qlg = g_Ql + hb;
    const __half* Kg  = g_K1 + hb;
    const __half* Vg  = g_V1 + hb;

    // ---- issue Q tile loads (hi/lo): 2048 x 16B chunks ----
#pragma unroll
    for (int it = 0; it < 8; it++) {
        int flat = tid + it * 256;
        int tile = flat >> 10, rem = flat & 1023;
        int row = rem >> 3, c8 = rem & 7;
        const __half* src = (tile == 0 ? Qhg : Qlg) + (size_t)(q0 + row) * DK_ + c8 * 8;
        cp_async16(smbase + tile * QTILE + row * (KPAD * 2) + c8 * 16, src);
    }
    cp_commit();

    auto issue_stage = [&](int t) {
        const int k0t = t * KT;
        const uint32_t st = smbase + AQBYTES + (t & 1) * ASTAGE;
#pragma unroll
        for (int it = 0; it < 4; it++) {            // 1024 x 16B chunks (K + V)
            int flat = tid + it * 256;
            int tile = flat >> 9, rem = flat & 511;
            int row = rem >> 3, c8 = rem & 7;
            const __half* src = (tile == 0 ? Kg : Vg) + (size_t)(k0t + row) * DK_ + c8 * 8;
            cp_async16(st + tile * ATILE + row * (KPAD * 2) + c8 * 16, src);
        }
        cp_commit();
    };

    issue_stage(0);

    uint32_t qh[4][4], ql[4][4];
    float o[8][4];
#pragma unroll
    for (int i = 0; i < 8; i++)
#pragma unroll
        for (int j = 0; j < 4; j++) o[i][j] = 0.f;
    float m0 = -1e30f, m1 = -1e30f, l0 = 0.f, l1 = 0.f;

    const int tr = lane >> 2, tc2 = (lane & 3) * 2;

#pragma unroll 1
    for (int t = 0; t < S_ / KT; t++) {
        if (t + 1 < S_ / KT) { issue_stage(t + 1); cp_wait<1>(); }
        else                 { cp_wait<0>(); }
        __syncthreads();

        if (t == 0) {
            const int arow = wid * 16 + (lane & 15);
            const int acol = (lane >> 4) * 8;
#pragma unroll
            for (int kt = 0; kt < 4; kt++) {
                uint32_t off = (arow * KPAD + kt * 16 + acol) * 2;
                ldm_x4(qh[kt][0], qh[kt][1], qh[kt][2], qh[kt][3], smbase + off);
                ldm_x4(ql[kt][0], ql[kt][1], ql[kt][2], ql[kt][3], smbase + QTILE + off);
            }
        }

        const uint32_t kb = smbase + AQBYTES + (t & 1) * ASTAGE;

        // ---- QK^T: scores [16 q x 64 k] per warp, 2-term (qh + ql) x K ----
        float sc[8][4];
#pragma unroll
        for (int i = 0; i < 8; i++)
#pragma unroll
            for (int j = 0; j < 4; j++) sc[i][j] = 0.f;

#pragma unroll
        for (int kt = 0; kt < 4; kt++) {
            const int brow = ((lane >> 4) & 1) * 8 + (lane & 7);
            const int bcol = kt * 16 + ((lane >> 3) & 1) * 8;
#pragma unroll
            for (int g = 0; g < 4; g++) {
                uint32_t off = ((g * 16 + brow) * KPAD + bcol) * 2;
                uint32_t bv[4];
                ldm_x4(bv[0], bv[1], bv[2], bv[3], kb + off);
                mma_f16(sc[2 * g + 0], qh[kt], bv + 0);
                mma_f16(sc[2 * g + 0], ql[kt], bv + 0);
                mma_f16(sc[2 * g + 1], qh[kt], bv + 2);
                mma_f16(sc[2 * g + 1], ql[kt], bv + 2);
            }
        }

        // ---- mask + online softmax ----
        const int2* mrow2 = (const int2*)(mask + b * S_ + t * KT);
        float mx0 = -3.4e38f, mx1 = -3.4e38f;
#pragma unroll
        for (int nt = 0; nt < 8; nt++) {
            int2 mv = mrow2[nt * 4 + (lane & 3)];
            if (mv.x == 0) { sc[nt][0] += NEGB; sc[nt][2] += NEGB; }
            if (mv.y == 0) { sc[nt][1] += NEGB; sc[nt][3] += NEGB; }
            mx0 = fmaxf(mx0, fmaxf(sc[nt][0], sc[nt][1]));
            mx1 = fmaxf(mx1, fmaxf(sc[nt][2], sc[nt][3]));
        }
        mx0 = fmaxf(mx0, __shfl_xor_sync(0xffffffffu, mx0, 1));
        mx0 = fmaxf(mx0, __shfl_xor_sync(0xffffffffu, mx0, 2));
        mx1 = fmaxf(mx1, __shfl_xor_sync(0xffffffffu, mx1, 1));
        mx1 = fmaxf(mx1, __shfl_xor_sync(0xffffffffu, mx1, 2));

        float m0n = fmaxf(m0, mx0), m1n = fmaxf(m1, mx1);
        float c0 = ex2(m0 - m0n), c1 = ex2(m1 - m1n);
        m0 = m0n; m1 = m1n;

        float sum0 = 0.f, sum1 = 0.f;
#pragma unroll
        for (int nt = 0; nt < 8; nt++) {
            sc[nt][0] = ex2(sc[nt][0] - m0n);
            sc[nt][1] = ex2(sc[nt][1] - m0n);
            sc[nt][2] = ex2(sc[nt][2] - m1n);
            sc[nt][3] = ex2(sc[nt][3] - m1n);
            sum0 += sc[nt][0] + sc[nt][1];
            sum1 += sc[nt][2] + sc[nt][3];
        }
        sum0 += __shfl_xor_sync(0xffffffffu, sum0, 1);
        sum0 += __shfl_xor_sync(0xffffffffu, sum0, 2);
        sum1 += __shfl_xor_sync(0xffffffffu, sum1, 1);
        sum1 += __shfl_xor_sync(0xffffffffu, sum1, 2);
        l0 = l0 * c0 + sum0;
        l1 = l1 * c1 + sum1;

        // rescale O
#pragma unroll
        for (int i = 0; i < 8; i++) {
            o[i][0] *= c0; o[i][1] *= c0;
            o[i][2] *= c1; o[i][3] *= c1;
        }

        // ---- P @ V: 2-term (ph + pl) x V (single fp16, ldmatrix.trans) ----
#pragma unroll
        for (int kk = 0; kk < 4; kk++) {
            uint32_t ph[4], pl[4];
            split2(sc[2 * kk + 0][0], sc[2 * kk + 0][1], ph[0], pl[0]);
            split2(sc[2 * kk + 0][2], sc[2 * kk + 0][3], ph[1], pl[1]);
            split2(sc[2 * kk + 1][0], sc[2 * kk + 1][1], ph[2], pl[2]);
            split2(sc[2 * kk + 1][2], sc[2 * kk + 1][3], ph[3], pl[3]);

            const int krow = kk * 16 + ((lane >> 3) & 1) * 8 + (lane & 7);
            const int dcol = ((lane >> 4) & 1) * 8;
#pragma unroll
            for (int g = 0; g < 4; g++) {
                uint32_t off = (krow * KPAD + g * 16 + dcol) * 2;
                uint32_t bv[4];
                ldm_x4_t(bv[0], bv[1], bv[2], bv[3], kb + ATILE + off);
                mma_f16(o[2 * g + 0], ph, bv + 0);
                mma_f16(o[2 * g + 0], pl, bv + 0);
                mma_f16(o[2 * g + 1], ph, bv + 2);
                mma_f16(o[2 * g + 1], pl, bv + 2);
            }
        }
        __syncthreads();
    }

    // ---- epilogue: O / l -> fp16 hi/lo ctx ----
    const float inv0 = 1.f / l0, inv1 = 1.f / l1;
    const int r0 = q0 + wid * 16 + tr;
    const size_t base0 = ((size_t)(b * S_ + r0)) * D_ + h * DK_;
    const size_t base1 = ((size_t)(b * S_ + r0 + 8)) * D_ + h * DK_;
#pragma unroll
    for (int nt = 0; nt < 8; nt++) {
        const int d0 = nt * 8 + tc2;
        uint32_t phi, plo;
        split2(o[nt][0] * inv0, o[nt][1] * inv0, phi, plo);
        *(uint32_t*)&g_ctxH[base0 + d0] = phi;
        *(uint32_t*)&g_ctxL[base0 + d0] = plo;
        split2(o[nt][2] * inv1, o[nt][3] * inv1, phi, plo);
        *(uint32_t*)&g_ctxH[base1 + d0] = phi;
        *(uint32_t*)&g_ctxL[base1 + d0] = plo;
    }
}

// ==================== launch ====================
extern "C" void kernel_launch(void* const* d_in, const int* in_sizes, int n_in,
                              void* d_out, int out_size) {
    const float* query = (const float*)d_in[0];
    const float* key   = (const float*)d_in[1];
    const float* value = (const float*)d_in[2];
    const int*   mask  = (const int*)d_in[3];
    const float* Wq = (const float*)d_in[4];
    const float* bq = (const float*)d_in[5];
    const float* Wk = (const float*)d_in[6];
    const float* bk = (const float*)d_in[7];
    const float* Wv = (const float*)d_in[8];
    const float* bv = (const float*)d_in[9];
    const float* Wo = (const float*)d_in[10];
    const float* bo = (const float*)d_in[11];
    float* out = (float*)d_out;

    cudaFuncSetAttribute(gemm_qkv_kernel, cudaFuncAttributeMaxDynamicSharedMemorySize, GSMEM);
    cudaFuncSetAttribute(gemm_out_kernel, cudaFuncAttributeMaxDynamicSharedMemorySize, GSMEM);
    cudaFuncSetAttribute(attn_mma_kernel, cudaFuncAttributeMaxDynamicSharedMemorySize, ASMEM);

    // weight transpose + fp16 split (one launch, z = 4)
    dim3 wtg(D_ / 32, D_ / 32, 4), wtb(32, 8);
    conv_wT_kernel<<<wtg, wtb>>>(Wq, Wk, Wv, Wo);

    // activation fp16 split (one launch, z = 3)
    dim3 cg((M_ * D_ / 4) / 256, 1, 3);
    conv_hl_kernel<<<cg, 256>>>(query, key, value);

    // QKV projections merged into one launch (z = 3)
    dim3 gq(D_ / BN, M_ / BM, 3);            // (8, 32, 3) = 768 CTAs
    gemm_qkv_kernel<<<gq, 256, GSMEM>>>(bq, bk, bv);

    // flash attention on tensor cores
    dim3 ga(S_ / 128, B_ * H_);              // (16, 32)
    attn_mma_kernel<<<ga, 256, ASMEM>>>(mask);

    // output projection
    dim3 gg(D_ / BN, M_ / BM);               // (8, 32)
    gemm_out_kernel<<<gg, 256, GSMEM>>>(bo, out);
}

// round 13
// speedup vs baseline: 1.3893x; 1.1621x over previous
#include <cuda_runtime.h>
#include <cuda_fp16.h>
#include <cstdint>

// Problem constants (match reference setup_inputs)
constexpr int B_ = 2;
constexpr int H_ = 16;
constexpr int S_ = 2048;
constexpr int D_ = 1024;     // d_model
constexpr int DK_ = 64;      // head dim
constexpr int M_ = B_ * S_;  // 4096 rows in all GEMMs

// Q pre-scale: 1/sqrt(Dk) * log2(e) so softmax uses exp2 directly
#define QSCALE 0.18033688011112042f
#define NEGB  (-1.0e8f)

// ==================== PTX helpers (sm_80-baseline only) ====================
__device__ __forceinline__ uint32_t smem_to_u32(const void* p) {
    uint32_t a;
    asm("{ .reg .u64 t; cvta.to.shared.u64 t, %1; cvt.u32.u64 %0, t; }" : "=r"(a) : "l"(p));
    return a;
}
__device__ __forceinline__ void cp_async16(uint32_t dst, const void* src) {
    asm volatile("cp.async.cg.shared.global [%0], [%1], 16;" :: "r"(dst), "l"(src));
}
__device__ __forceinline__ void cp_commit() {
    asm volatile("cp.async.commit_group;");
}
template <int N>
__device__ __forceinline__ void cp_wait() {
    asm volatile("cp.async.wait_group %0;" :: "n"(N));
}
__device__ __forceinline__ void ldm_x4(uint32_t& r0, uint32_t& r1, uint32_t& r2, uint32_t& r3,
                                       uint32_t addr) {
    asm volatile("ldmatrix.sync.aligned.m8n8.x4.shared.b16 {%0,%1,%2,%3}, [%4];"
                 : "=r"(r0), "=r"(r1), "=r"(r2), "=r"(r3) : "r"(addr));
}
__device__ __forceinline__ void ldm_x4_t(uint32_t& r0, uint32_t& r1, uint32_t& r2, uint32_t& r3,
                                         uint32_t addr) {
    asm volatile("ldmatrix.sync.aligned.m8n8.x4.trans.shared.b16 {%0,%1,%2,%3}, [%4];"
                 : "=r"(r0), "=r"(r1), "=r"(r2), "=r"(r3) : "r"(addr));
}
__device__ __forceinline__ void mma_f16(float* c, const uint32_t* a, const uint32_t* b) {
    asm volatile(
        "mma.sync.aligned.m16n8k16.row.col.f32.f16.f16.f32 "
        "{%0,%1,%2,%3}, {%4,%5,%6,%7}, {%8,%9}, {%0,%1,%2,%3};"
        : "+f"(c[0]), "+f"(c[1]), "+f"(c[2]), "+f"(c[3])
        : "r"(a[0]), "r"(a[1]), "r"(a[2]), "r"(a[3]), "r"(b[0]), "r"(b[1]));
}
__device__ __forceinline__ float ex2(float x) {
    float y;
    asm("ex2.approx.f32 %0, %1;" : "=f"(y) : "f"(x));
    return y;
}
// split (a,b) fp32 pair into packed fp16x2 hi + lo
__device__ __forceinline__ void split2(float a, float b, uint32_t& hi, uint32_t& lo) {
    __half2 h = __floats2half2_rn(a, b);
    float2 hf = __half22float2(h);
    __half2 l = __floats2half2_rn(a - hf.x, b - hf.y);
    hi = *(uint32_t*)&h;
    lo = *(uint32_t*)&l;
}
__device__ __forceinline__ uint32_t pack2(float a, float b) {
    __half2 h = __floats2half2_rn(a, b);
    return *(uint32_t*)&h;
}

// -------------------- device scratch (no allocations allowed) --------------------
__device__ __half g_Q1[(size_t)B_ * H_ * S_ * DK_];   // Q single fp16 (pre-scaled)
__device__ __half g_K1[(size_t)B_ * H_ * S_ * DK_];   // K single fp16
__device__ __half g_V1[(size_t)B_ * H_ * S_ * DK_];   // V single fp16
__device__ __half g_ctxH[(size_t)M_ * D_];
__device__ __half g_ctxL[(size_t)M_ * D_];
__device__ __half g_actH[3][(size_t)M_ * D_];
__device__ __half g_actL[3][(size_t)M_ * D_];
__device__ __half g_wTH[4][(size_t)D_ * D_];
__device__ __half g_wTL[4][(size_t)D_ * D_];

// ==================== conversion kernels (z-merged) ====================
__global__ __launch_bounds__(256) void conv_hl_kernel(const float* __restrict__ q,
                                                      const float* __restrict__ k,
                                                      const float* __restrict__ v) {
    const int which = blockIdx.z;
    const float* src = (which == 0) ? q : (which == 1) ? k : v;
    __half* hi = g_actH[which];
    __half* lo = g_actL[which];
    int i = blockIdx.x * blockDim.x + threadIdx.x;   // float4 index
    float4 val = ((const float4*)src)[i];
    uint32_t h0, l0, h1, l1;
    split2(val.x, val.y, h0, l0);
    split2(val.z, val.w, h1, l1);
    ((uint32_t*)hi)[i * 2 + 0] = h0;
    ((uint32_t*)hi)[i * 2 + 1] = h1;
    ((uint32_t*)lo)[i * 2 + 0] = l0;
    ((uint32_t*)lo)[i * 2 + 1] = l1;
}

// W [K,N] fp32 -> transposed hi/lo fp16 [N,K]; z selects which of 4 weights
__global__ __launch_bounds__(256) void conv_wT_kernel(const float* __restrict__ Wq,
                                                      const float* __restrict__ Wk,
                                                      const float* __restrict__ Wv,
                                                      const float* __restrict__ Wo) {
    __shared__ float t[32][33];
    const int which = blockIdx.z;
    const float* W = (which == 0) ? Wq : (which == 1) ? Wk : (which == 2) ? Wv : Wo;
    const int n0 = blockIdx.x * 32, k0 = blockIdx.y * 32;
    const int tx = threadIdx.x, ty = threadIdx.y;     // block (32,8)
#pragma unroll
    for (int r = 0; r < 32; r += 8)
        t[ty + r][tx] = W[(size_t)(k0 + ty + r) * D_ + n0 + tx];
    __syncthreads();
    __half* hi = g_wTH[which];
    __half* lo = g_wTL[which];
#pragma unroll
    for (int r = 0; r < 32; r += 8) {
        float v = t[tx][ty + r];
        __half h = __float2half_rn(v);
        __half l = __float2half_rn(v - __half2float(h));
        size_t o = (size_t)(n0 + ty + r) * D_ + k0 + tx;
        hi[o] = h; lo[o] = l;
    }
}

// ==================== mma.sync GEMM mainloop (3x fp16 split) ====================
constexpr int BM = 128, BN = 128, BK = 32;
constexpr int TPAD = 40;
constexpr int TILE_B = 128 * TPAD * 2;
constexpr int STAGE_B = 4 * TILE_B;
constexpr int GSMEM = 2 * STAGE_B;
constexpr int NC = D_ / BK;

__device__ __forceinline__ void gemm_mainloop(float (&acc)[2][8][4],
                                              const __half* __restrict__ Ah,
                                              const __half* __restrict__ Al,
                                              const __half* __restrict__ Bh,
                                              const __half* __restrict__ Bl,
                                              int m0, int n0, uint32_t smbase,
                                              int tid, int lane, int wm, int wn) {
    auto issue_load = [&](int c) {
        const int s = c & 1, k0 = c * BK;
        const uint32_t st = smbase + s * STAGE_B;
#pragma unroll
        for (int t = 0; t < 8; t++) {
            int i = tid + t * 256;
            int tile = i >> 9, rem = i & 511, row = rem >> 2, cc = rem & 3;
            const __half* src;
            if (tile == 0)      src = Ah + (size_t)(m0 + row) * D_ + k0 + cc * 8;
            else if (tile == 1) src = Al + (size_t)(m0 + row) * D_ + k0 + cc * 8;
            else if (tile == 2) src = Bh + (size_t)(n0 + row) * D_ + k0 + cc * 8;
            else                src = Bl + (size_t)(n0 + row) * D_ + k0 + cc * 8;
            cp_async16(st + tile * TILE_B + (row * TPAD + cc * 8) * 2, src);
        }
        cp_commit();
    };

    issue_load(0);

    for (int c = 0; c < NC; c++) {
        if (c + 1 < NC) { issue_load(c + 1); cp_wait<1>(); }
        else            { cp_wait<0>(); }
        __syncthreads();

        const uint32_t st = smbase + (c & 1) * STAGE_B;
#pragma unroll
        for (int k16 = 0; k16 < BK; k16 += 16) {
            uint32_t a_hi[2][4], a_lo[2][4];
            const int arow = wm + (lane & 15);
            const int acol = k16 + (lane >> 4) * 8;
#pragma unroll
            for (int i = 0; i < 2; i++) {
                uint32_t off = ((arow + i * 16) * TPAD + acol) * 2;
                ldm_x4(a_hi[i][0], a_hi[i][1], a_hi[i][2], a_hi[i][3], st + off);
                ldm_x4(a_lo[i][0], a_lo[i][1], a_lo[i][2], a_lo[i][3], st + TILE_B + off);
            }
            const int brow_base = wn + ((lane >> 4) & 1) * 8 + (lane & 7);
            const int bcol = k16 + ((lane >> 3) & 1) * 8;
#pragma unroll
            for (int jj = 0; jj < 4; jj++) {
                uint32_t off = ((brow_base + jj * 16) * TPAD + bcol) * 2;
                uint32_t bh[4], bl[4];
                ldm_x4(bh[0], bh[1], bh[2], bh[3], st + 2 * TILE_B + off);
                ldm_x4(bl[0], bl[1], bl[2], bl[3], st + 3 * TILE_B + off);
#pragma unroll
                for (int i = 0; i < 2; i++) {
                    mma_f16(acc[i][2 * jj + 0], a_hi[i], bh + 0);
                    mma_f16(acc[i][2 * jj + 0], a_lo[i], bh + 0);
                    mma_f16(acc[i][2 * jj + 0], a_hi[i], bl + 0);
                    mma_f16(acc[i][2 * jj + 1], a_hi[i], bh + 2);
                    mma_f16(acc[i][2 * jj + 1], a_lo[i], bh + 2);
                    mma_f16(acc[i][2 * jj + 1], a_hi[i], bl + 2);
                }
            }
        }
        __syncthreads();
    }
}

// QKV projections merged: blockIdx.z selects target; all emit single fp16
__global__ __launch_bounds__(256, 2) void gemm_qkv_kernel(const float* __restrict__ bq,
                                                          const float* __restrict__ bk,
                                                          const float* __restrict__ bv) {
    extern __shared__ __align__(128) char sm[];
    const uint32_t smbase = smem_to_u32(sm);
    const int tid = threadIdx.x, wid = tid >> 5, lane = tid & 31;
    const int m0 = blockIdx.y * BM, n0 = blockIdx.x * BN;
    const int wm = (wid & 3) * 32, wn = (wid >> 2) * 64;
    const int tgt = blockIdx.z;
    const float* bias = (tgt == 0) ? bq : (tgt == 1) ? bk : bv;

    float acc[2][8][4];
#pragma unroll
    for (int i = 0; i < 2; i++)
#pragma unroll
        for (int j = 0; j < 8; j++)
#pragma unroll
            for (int q = 0; q < 4; q++) acc[i][j][q] = 0.f;

    gemm_mainloop(acc, g_actH[tgt], g_actL[tgt], g_wTH[tgt], g_wTL[tgt],
                  m0, n0, smbase, tid, lane, wm, wn);

    const int tr = lane >> 2, tc = (lane & 3) * 2;
    const int hd = (n0 + wn) >> 6;
    __half* dst = (tgt == 0) ? g_Q1 : (tgt == 1) ? g_K1 : g_V1;
    const float sc = (tgt == 0) ? QSCALE : 1.0f;
#pragma unroll
    for (int i = 0; i < 2; i++) {
#pragma unroll
        for (int hh = 0; hh < 2; hh++) {
            const int m = m0 + wm + i * 16 + tr + hh * 8;
            const int b = m >> 11, sq = m & (S_ - 1);
            const size_t rowbase = ((size_t)((b * H_ + hd) * S_ + sq)) * DK_;
#pragma unroll
            for (int j = 0; j < 8; j++) {
                const int n = n0 + wn + j * 8 + tc;
                uint32_t hv = pack2((acc[i][j][hh * 2 + 0] + bias[n]) * sc,
                                    (acc[i][j][hh * 2 + 1] + bias[n + 1]) * sc);
                *(uint32_t*)&dst[rowbase + j * 8 + tc] = hv;
            }
        }
    }
}

// Output projection: reads ctx hi/lo, writes fp32
__global__ __launch_bounds__(256, 2) void gemm_out_kernel(const float* __restrict__ bias,
                                                          float* __restrict__ outp) {
    extern __shared__ __align__(128) char sm[];
    const uint32_t smbase = smem_to_u32(sm);
    const int tid = threadIdx.x, wid = tid >> 5, lane = tid & 31;
    const int m0 = blockIdx.y * BM, n0 = blockIdx.x * BN;
    const int wm = (wid & 3) * 32, wn = (wid >> 2) * 64;

    float acc[2][8][4];
#pragma unroll
    for (int i = 0; i < 2; i++)
#pragma unroll
        for (int j = 0; j < 8; j++)
#pragma unroll
            for (int q = 0; q < 4; q++) acc[i][j][q] = 0.f;

    gemm_mainloop(acc, g_ctxH, g_ctxL, g_wTH[3], g_wTL[3],
                  m0, n0, smbase, tid, lane, wm, wn);

    const int tr = lane >> 2, tc = (lane & 3) * 2;
#pragma unroll
    for (int i = 0; i < 2; i++) {
#pragma unroll
        for (int hh = 0; hh < 2; hh++) {
            const int m = m0 + wm + i * 16 + tr + hh * 8;
            float* p = outp + (size_t)m * D_ + n0 + wn + tc;
#pragma unroll
            for (int j = 0; j < 8; j++) {
                const int n = n0 + wn + j * 8 + tc;
                float2 o;
                o.x = acc[i][j][hh * 2 + 0] + bias[n];
                o.y = acc[i][j][hh * 2 + 1] + bias[n + 1];
                *(float2*)(p + j * 8) = o;
            }
        }
    }
}

// ==================== mma.sync flash attention (fp16, single-term) ====================
// CTA: 128 q-rows, 8 warps (16 q-rows each), key tile 64.
// Q, K, V, P all single fp16 (errors ~2^-11 each, RSS well under 1e-3).
constexpr int KT = 64;
constexpr int KPAD = 72;                          // padded row (halves), 144 B
constexpr int QTILE = 128 * KPAD * 2;             // 18432 B
constexpr int ATILE = KT * KPAD * 2;              // 9216 B
constexpr int ASTAGE = 2 * ATILE;                 // K, V = 18432 B
constexpr int ASMEM = QTILE + 2 * ASTAGE;         // 55296 B

__global__ __launch_bounds__(256, 2) void attn_mma_kernel(const int* __restrict__ mask) {
    extern __shared__ __align__(128) char smem_raw[];
    const uint32_t smbase = smem_to_u32(smem_raw);
    const int tid = threadIdx.x, wid = tid >> 5, lane = tid & 31;
    const int bh = blockIdx.y, b = bh >> 4, h = bh & 15;
    const int q0 = blockIdx.x * 128;

    const size_t hb = (size_t)bh * S_ * DK_;
    const __half* Qg = g_Q1 + hb;
    const __half* Kg = g_K1 + hb;
    const __half* Vg = g_V1 + hb;

    // ---- issue Q tile loads: 1024 x 16B chunks ----
#pragma unroll
    for (int it = 0; it < 4; it++) {
        int flat = tid + it * 256;
        int row = flat >> 3, c8 = flat & 7;
        cp_async16(smbase + row * (KPAD * 2) + c8 * 16,
                   Qg + (size_t)(q0 + row) * DK_ + c8 * 8);
    }
    cp_commit();

    auto issue_stage = [&](int t) {
        const int k0t = t * KT;
        const uint32_t st = smbase + QTILE + (t & 1) * ASTAGE;
#pragma unroll
        for (int it = 0; it < 4; it++) {            // 1024 x 16B chunks (K + V)
            int flat = tid + it * 256;
            int tile = flat >> 9, rem = flat & 511;
            int row = rem >> 3, c8 = rem & 7;
            const __half* src = (tile == 0 ? Kg : Vg) + (size_t)(k0t + row) * DK_ + c8 * 8;
            cp_async16(st + tile * ATILE + row * (KPAD * 2) + c8 * 16, src);
        }
        cp_commit();
    };

    issue_stage(0);

    uint32_t qh[4][4];
    float o[8][4];
#pragma unroll
    for (int i = 0; i < 8; i++)
#pragma unroll
        for (int j = 0; j < 4; j++) o[i][j] = 0.f;
    float m0 = -1e30f, m1 = -1e30f, l0 = 0.f, l1 = 0.f;

    const int tr = lane >> 2, tc2 = (lane & 3) * 2;

#pragma unroll 1
    for (int t = 0; t < S_ / KT; t++) {
        if (t + 1 < S_ / KT) { issue_stage(t + 1); cp_wait<1>(); }
        else                 { cp_wait<0>(); }
        __syncthreads();

        if (t == 0) {
            const int arow = wid * 16 + (lane & 15);
            const int acol = (lane >> 4) * 8;
#pragma unroll
            for (int kt = 0; kt < 4; kt++) {
                uint32_t off = (arow * KPAD + kt * 16 + acol) * 2;
                ldm_x4(qh[kt][0], qh[kt][1], qh[kt][2], qh[kt][3], smbase + off);
            }
        }

        const uint32_t kb = smbase + QTILE + (t & 1) * ASTAGE;

        // ---- QK^T: scores [16 q x 64 k] per warp, single-term ----
        float sc[8][4];
#pragma unroll
        for (int i = 0; i < 8; i++)
#pragma unroll
            for (int j = 0; j < 4; j++) sc[i][j] = 0.f;

#pragma unroll
        for (int kt = 0; kt < 4; kt++) {
            const int brow = ((lane >> 4) & 1) * 8 + (lane & 7);
            const int bcol = kt * 16 + ((lane >> 3) & 1) * 8;
#pragma unroll
            for (int g = 0; g < 4; g++) {
                uint32_t off = ((g * 16 + brow) * KPAD + bcol) * 2;
                uint32_t bv[4];
                ldm_x4(bv[0], bv[1], bv[2], bv[3], kb + off);
                mma_f16(sc[2 * g + 0], qh[kt], bv + 0);
                mma_f16(sc[2 * g + 1], qh[kt], bv + 2);
            }
        }

        // ---- mask + online softmax ----
        const int2* mrow2 = (const int2*)(mask + b * S_ + t * KT);
        float mx0 = -3.4e38f, mx1 = -3.4e38f;
#pragma unroll
        for (int nt = 0; nt < 8; nt++) {
            int2 mv = mrow2[nt * 4 + (lane & 3)];
            if (mv.x == 0) { sc[nt][0] += NEGB; sc[nt][2] += NEGB; }
            if (mv.y == 0) { sc[nt][1] += NEGB; sc[nt][3] += NEGB; }
            mx0 = fmaxf(mx0, fmaxf(sc[nt][0], sc[nt][1]));
            mx1 = fmaxf(mx1, fmaxf(sc[nt][2], sc[nt][3]));
        }
        mx0 = fmaxf(mx0, __shfl_xor_sync(0xffffffffu, mx0, 1));
        mx0 = fmaxf(mx0, __shfl_xor_sync(0xffffffffu, mx0, 2));
        mx1 = fmaxf(mx1, __shfl_xor_sync(0xffffffffu, mx1, 1));
        mx1 = fmaxf(mx1, __shfl_xor_sync(0xffffffffu, mx1, 2));

        float m0n = fmaxf(m0, mx0), m1n = fmaxf(m1, mx1);
        float c0 = ex2(m0 - m0n), c1 = ex2(m1 - m1n);
        m0 = m0n; m1 = m1n;

        float sum0 = 0.f, sum1 = 0.f;
#pragma unroll
        for (int nt = 0; nt < 8; nt++) {
            sc[nt][0] = ex2(sc[nt][0] - m0n);
            sc[nt][1] = ex2(sc[nt][1] - m0n);
            sc[nt][2] = ex2(sc[nt][2] - m1n);
            sc[nt][3] = ex2(sc[nt][3] - m1n);
            sum0 += sc[nt][0] + sc[nt][1];
            sum1 += sc[nt][2] + sc[nt][3];
        }
        sum0 += __shfl_xor_sync(0xffffffffu, sum0, 1);
        sum0 += __shfl_xor_sync(0xffffffffu, sum0, 2);
        sum1 += __shfl_xor_sync(0xffffffffu, sum1, 1);
        sum1 += __shfl_xor_sync(0xffffffffu, sum1, 2);
        l0 = l0 * c0 + sum0;
        l1 = l1 * c1 + sum1;

        // rescale O
#pragma unroll
        for (int i = 0; i < 8; i++) {
            o[i][0] *= c0; o[i][1] *= c0;
            o[i][2] *= c1; o[i][3] *= c1;
        }

        // ---- P @ V: single-term fp16 P x V (ldmatrix.trans) ----
#pragma unroll
        for (int kk = 0; kk < 4; kk++) {
            uint32_t ph[4];
            ph[0] = pack2(sc[2 * kk + 0][0], sc[2 * kk + 0][1]);
            ph[1] = pack2(sc[2 * kk + 0][2], sc[2 * kk + 0][3]);
            ph[2] = pack2(sc[2 * kk + 1][0], sc[2 * kk + 1][1]);
            ph[3] = pack2(sc[2 * kk + 1][2], sc[2 * kk + 1][3]);

            const int krow = kk * 16 + ((lane >> 3) & 1) * 8 + (lane & 7);
            const int dcol = ((lane >> 4) & 1) * 8;
#pragma unroll
            for (int g = 0; g < 4; g++) {
                uint32_t off = (krow * KPAD + g * 16 + dcol) * 2;
                uint32_t bv[4];
                ldm_x4_t(bv[0], bv[1], bv[2], bv[3], kb + ATILE + off);
                mma_f16(o[2 * g + 0], ph, bv + 0);
                mma_f16(o[2 * g + 1], ph, bv + 2);
            }
        }
        __syncthreads();
    }

    // ---- epilogue: O / l -> fp16 hi/lo ctx ----
    const float inv0 = 1.f / l0, inv1 = 1.f / l1;
    const int r0 = q0 + wid * 16 + tr;
    const size_t base0 = ((size_t)(b * S_ + r0)) * D_ + h * DK_;
    const size_t base1 = ((size_t)(b * S_ + r0 + 8)) * D_ + h * DK_;
#pragma unroll
    for (int nt = 0; nt < 8; nt++) {
        const int d0 = nt * 8 + tc2;
        uint32_t phi, plo;
        split2(o[nt][0] * inv0, o[nt][1] * inv0, phi, plo);
        *(uint32_t*)&g_ctxH[base0 + d0] = phi;
        *(uint32_t*)&g_ctxL[base0 + d0] = plo;
        split2(o[nt][2] * inv1, o[nt][3] * inv1, phi, plo);
        *(uint32_t*)&g_ctxH[base1 + d0] = phi;
        *(uint32_t*)&g_ctxL[base1 + d0] = plo;
    }
}

// ==================== launch ====================
extern "C" void kernel_launch(void* const* d_in, const int* in_sizes, int n_in,
                              void* d_out, int out_size) {
    const float* query = (const float*)d_in[0];
    const float* key   = (const float*)d_in[1];
    const float* value = (const float*)d_in[2];
    const int*   mask  = (const int*)d_in[3];
    const float* Wq = (const float*)d_in[4];
    const float* bq = (const float*)d_in[5];
    const float* Wk = (const float*)d_in[6];
    const float* bk = (const float*)d_in[7];
    const float* Wv = (const float*)d_in[8];
    const float* bv = (const float*)d_in[9];
    const float* Wo = (const float*)d_in[10];
    const float* bo = (const float*)d_in[11];
    float* out = (float*)d_out;

    cudaFuncSetAttribute(gemm_qkv_kernel, cudaFuncAttributeMaxDynamicSharedMemorySize, GSMEM);
    cudaFuncSetAttribute(gemm_out_kernel, cudaFuncAttributeMaxDynamicSharedMemorySize, GSMEM);
    cudaFuncSetAttribute(attn_mma_kernel, cudaFuncAttributeMaxDynamicSharedMemorySize, ASMEM);

    // weight transpose + fp16 split (one launch, z = 4)
    dim3 wtg(D_ / 32, D_ / 32, 4), wtb(32, 8);
    conv_wT_kernel<<<wtg, wtb>>>(Wq, Wk, Wv, Wo);

    // activation fp16 split (one launch, z = 3)
    dim3 cg((M_ * D_ / 4) / 256, 1, 3);
    conv_hl_kernel<<<cg, 256>>>(query, key, value);

    // QKV projections merged into one launch (z = 3)
    dim3 gq(D_ / BN, M_ / BM, 3);            // (8, 32, 3) = 768 CTAs
    gemm_qkv_kernel<<<gq, 256, GSMEM>>>(bq, bk, bv);

    // flash attention on tensor cores
    dim3 ga(S_ / 128, B_ * H_);              // (16, 32)
    attn_mma_kernel<<<ga, 256, ASMEM>>>(mask);

    // output projection
    dim3 gg(D_ / BN, M_ / BM);               // (8, 32)
    gemm_out_kernel<<<gg, 256, GSMEM>>>(bo, out);
}

// round 14
// speedup vs baseline: 1.7468x; 1.2573x over previous
#include <cuda_runtime.h>
#include <cuda_fp16.h>
#include <cstdint>

// Problem constants (match reference setup_inputs)
constexpr int B_ = 2;
constexpr int H_ = 16;
constexpr int S_ = 2048;
constexpr int D_ = 1024;     // d_model
constexpr int DK_ = 64;      // head dim
constexpr int M_ = B_ * S_;  // 4096 rows in all GEMMs

// Q pre-scale: 1/sqrt(Dk) * log2(e) so softmax uses exp2 directly
#define QSCALE 0.18033688011112042f
#define NEGB  (-1.0e8f)

// ==================== PTX helpers (sm_80-baseline only) ====================
__device__ __forceinline__ uint32_t smem_to_u32(const void* p) {
    uint32_t a;
    asm("{ .reg .u64 t; cvta.to.shared.u64 t, %1; cvt.u32.u64 %0, t; }" : "=r"(a) : "l"(p));
    return a;
}
__device__ __forceinline__ void cp_async16(uint32_t dst, const void* src) {
    asm volatile("cp.async.cg.shared.global [%0], [%1], 16;" :: "r"(dst), "l"(src));
}
__device__ __forceinline__ void cp_commit() {
    asm volatile("cp.async.commit_group;");
}
template <int N>
__device__ __forceinline__ void cp_wait() {
    asm volatile("cp.async.wait_group %0;" :: "n"(N));
}
__device__ __forceinline__ void ldm_x4(uint32_t& r0, uint32_t& r1, uint32_t& r2, uint32_t& r3,
                                       uint32_t addr) {
    asm volatile("ldmatrix.sync.aligned.m8n8.x4.shared.b16 {%0,%1,%2,%3}, [%4];"
                 : "=r"(r0), "=r"(r1), "=r"(r2), "=r"(r3) : "r"(addr));
}
__device__ __forceinline__ void ldm_x4_t(uint32_t& r0, uint32_t& r1, uint32_t& r2, uint32_t& r3,
                                         uint32_t addr) {
    asm volatile("ldmatrix.sync.aligned.m8n8.x4.trans.shared.b16 {%0,%1,%2,%3}, [%4];"
                 : "=r"(r0), "=r"(r1), "=r"(r2), "=r"(r3) : "r"(addr));
}
__device__ __forceinline__ void mma_f16(float* c, const uint32_t* a, const uint32_t* b) {
    asm volatile(
        "mma.sync.aligned.m16n8k16.row.col.f32.f16.f16.f32 "
        "{%0,%1,%2,%3}, {%4,%5,%6,%7}, {%8,%9}, {%0,%1,%2,%3};"
        : "+f"(c[0]), "+f"(c[1]), "+f"(c[2]), "+f"(c[3])
        : "r"(a[0]), "r"(a[1]), "r"(a[2]), "r"(a[3]), "r"(b[0]), "r"(b[1]));
}
__device__ __forceinline__ float ex2(float x) {
    float y;
    asm("ex2.approx.f32 %0, %1;" : "=f"(y) : "f"(x));
    return y;
}
// split (a,b) fp32 pair into packed fp16x2 hi + lo
__device__ __forceinline__ void split2(float a, float b, uint32_t& hi, uint32_t& lo) {
    __half2 h = __floats2half2_rn(a, b);
    float2 hf = __half22float2(h);
    __half2 l = __floats2half2_rn(a - hf.x, b - hf.y);
    hi = *(uint32_t*)&h;
    lo = *(uint32_t*)&l;
}
__device__ __forceinline__ uint32_t pack2(float a, float b) {
    __half2 h = __floats2half2_rn(a, b);
    return *(uint32_t*)&h;
}

// -------------------- device scratch (no allocations allowed) --------------------
__device__ __half g_Q1[(size_t)B_ * H_ * S_ * DK_];   // Q single fp16 (pre-scaled)
__device__ __half g_K1[(size_t)B_ * H_ * S_ * DK_];   // K single fp16
__device__ __half g_V1[(size_t)B_ * H_ * S_ * DK_];   // V single fp16
__device__ __half g_ctx1[(size_t)M_ * D_];            // ctx single fp16
__device__ __half g_act1[3][(size_t)M_ * D_];         // activations single fp16
__device__ __half g_wTH[4][(size_t)D_ * D_];          // weights hi (transposed [N,K])
__device__ __half g_wTL[4][(size_t)D_ * D_];          // weights lo

// ==================== conversion kernels (z-merged) ====================
// fp32 activations -> single fp16
__global__ __launch_bounds__(256) void conv_act_kernel(const float* __restrict__ q,
                                                       const float* __restrict__ k,
                                                       const float* __restrict__ v) {
    const int which = blockIdx.z;
    const float* src = (which == 0) ? q : (which == 1) ? k : v;
    __half* dst = g_act1[which];
    int i = blockIdx.x * blockDim.x + threadIdx.x;   // float4 index
    float4 val = ((const float4*)src)[i];
    uint2 o;
    o.x = pack2(val.x, val.y);
    o.y = pack2(val.z, val.w);
    ((uint2*)dst)[i] = o;
}

// W [K,N] fp32 -> transposed hi/lo fp16 [N,K]; z selects which of 4 weights
__global__ __launch_bounds__(256) void conv_wT_kernel(const float* __restrict__ Wq,
                                                      const float* __restrict__ Wk,
                                                      const float* __restrict__ Wv,
                                                      const float* __restrict__ Wo) {
    __shared__ float t[32][33];
    const int which = blockIdx.z;
    const float* W = (which == 0) ? Wq : (which == 1) ? Wk : (which == 2) ? Wv : Wo;
    const int n0 = blockIdx.x * 32, k0 = blockIdx.y * 32;
    const int tx = threadIdx.x, ty = threadIdx.y;     // block (32,8)
#pragma unroll
    for (int r = 0; r < 32; r += 8)
        t[ty + r][tx] = W[(size_t)(k0 + ty + r) * D_ + n0 + tx];
    __syncthreads();
    __half* hi = g_wTH[which];
    __half* lo = g_wTL[which];
#pragma unroll
    for (int r = 0; r < 32; r += 8) {
        float v = t[tx][ty + r];
        __half h = __float2half_rn(v);
        __half l = __float2half_rn(v - __half2float(h));
        size_t o = (size_t)(n0 + ty + r) * D_ + k0 + tx;
        hi[o] = h; lo[o] = l;
    }
}

// ==================== mma.sync GEMM mainloop (2-term: A*(Wh + Wl)) ====================
constexpr int BM = 128, BN = 128, BK = 32;
constexpr int TPAD = 40;
constexpr int TILE_B = 128 * TPAD * 2;          // 10240 B
constexpr int STAGE_B = 3 * TILE_B;             // A, Wh, Wl = 30720 B
constexpr int GSMEM = 2 * STAGE_B;              // 61440 B
constexpr int NC = D_ / BK;

__device__ __forceinline__ void gemm_mainloop(float (&acc)[2][8][4],
                                              const __half* __restrict__ A1,
                                              const __half* __restrict__ Bh,
                                              const __half* __restrict__ Bl,
                                              int m0, int n0, uint32_t smbase,
                                              int tid, int lane, int wm, int wn) {
    auto issue_load = [&](int c) {
        const int s = c & 1, k0 = c * BK;
        const uint32_t st = smbase + s * STAGE_B;
#pragma unroll
        for (int t = 0; t < 6; t++) {           // 1536 x 16B chunks
            int i = tid + t * 256;
            int tile = i >> 9, rem = i & 511, row = rem >> 2, cc = rem & 3;
            const __half* src;
            if (tile == 0)      src = A1 + (size_t)(m0 + row) * D_ + k0 + cc * 8;
            else if (tile == 1) src = Bh + (size_t)(n0 + row) * D_ + k0 + cc * 8;
            else                src = Bl + (size_t)(n0 + row) * D_ + k0 + cc * 8;
            cp_async16(st + tile * TILE_B + (row * TPAD + cc * 8) * 2, src);
        }
        cp_commit();
    };

    issue_load(0);

    for (int c = 0; c < NC; c++) {
        if (c + 1 < NC) { issue_load(c + 1); cp_wait<1>(); }
        else            { cp_wait<0>(); }
        __syncthreads();

        const uint32_t st = smbase + (c & 1) * STAGE_B;
#pragma unroll
        for (int k16 = 0; k16 < BK; k16 += 16) {
            uint32_t a1[2][4];
            const int arow = wm + (lane & 15);
            const int acol = k16 + (lane >> 4) * 8;
#pragma unroll
            for (int i = 0; i < 2; i++) {
                uint32_t off = ((arow + i * 16) * TPAD + acol) * 2;
                ldm_x4(a1[i][0], a1[i][1], a1[i][2], a1[i][3], st + off);
            }
            const int brow_base = wn + ((lane >> 4) & 1) * 8 + (lane & 7);
            const int bcol = k16 + ((lane >> 3) & 1) * 8;
#pragma unroll
            for (int jj = 0; jj < 4; jj++) {
                uint32_t off = ((brow_base + jj * 16) * TPAD + bcol) * 2;
                uint32_t bh[4], bl[4];
                ldm_x4(bh[0], bh[1], bh[2], bh[3], st + TILE_B + off);
                ldm_x4(bl[0], bl[1], bl[2], bl[3], st + 2 * TILE_B + off);
#pragma unroll
                for (int i = 0; i < 2; i++) {
                    mma_f16(acc[i][2 * jj + 0], a1[i], bh + 0);
                    mma_f16(acc[i][2 * jj + 0], a1[i], bl + 0);
                    mma_f16(acc[i][2 * jj + 1], a1[i], bh + 2);
                    mma_f16(acc[i][2 * jj + 1], a1[i], bl + 2);
                }
            }
        }
        __syncthreads();
    }
}

// QKV projections merged: blockIdx.z selects target; all emit single fp16
__global__ __launch_bounds__(256, 2) void gemm_qkv_kernel(const float* __restrict__ bq,
                                                          const float* __restrict__ bk,
                                                          const float* __restrict__ bv) {
    extern __shared__ __align__(128) char sm[];
    const uint32_t smbase = smem_to_u32(sm);
    const int tid = threadIdx.x, wid = tid >> 5, lane = tid & 31;
    const int m0 = blockIdx.y * BM, n0 = blockIdx.x * BN;
    const int wm = (wid & 3) * 32, wn = (wid >> 2) * 64;
    const int tgt = blockIdx.z;
    const float* bias = (tgt == 0) ? bq : (tgt == 1) ? bk : bv;

    float acc[2][8][4];
#pragma unroll
    for (int i = 0; i < 2; i++)
#pragma unroll
        for (int j = 0; j < 8; j++)
#pragma unroll
            for (int q = 0; q < 4; q++) acc[i][j][q] = 0.f;

    gemm_mainloop(acc, g_act1[tgt], g_wTH[tgt], g_wTL[tgt],
                  m0, n0, smbase, tid, lane, wm, wn);

    const int tr = lane >> 2, tc = (lane & 3) * 2;
    const int hd = (n0 + wn) >> 6;
    __half* dst = (tgt == 0) ? g_Q1 : (tgt == 1) ? g_K1 : g_V1;
    const float sc = (tgt == 0) ? QSCALE : 1.0f;
#pragma unroll
    for (int i = 0; i < 2; i++) {
#pragma unroll
        for (int hh = 0; hh < 2; hh++) {
            const int m = m0 + wm + i * 16 + tr + hh * 8;
            const int b = m >> 11, sq = m & (S_ - 1);
            const size_t rowbase = ((size_t)((b * H_ + hd) * S_ + sq)) * DK_;
#pragma unroll
            for (int j = 0; j < 8; j++) {
                const int n = n0 + wn + j * 8 + tc;
                uint32_t hv = pack2((acc[i][j][hh * 2 + 0] + bias[n]) * sc,
                                    (acc[i][j][hh * 2 + 1] + bias[n + 1]) * sc);
                *(uint32_t*)&dst[rowbase + j * 8 + tc] = hv;
            }
        }
    }
}

// Output projection: reads ctx single fp16, writes fp32
__global__ __launch_bounds__(256, 2) void gemm_out_kernel(const float* __restrict__ bias,
                                                          float* __restrict__ outp) {
    extern __shared__ __align__(128) char sm[];
    const uint32_t smbase = smem_to_u32(sm);
    const int tid = threadIdx.x, wid = tid >> 5, lane = tid & 31;
    const int m0 = blockIdx.y * BM, n0 = blockIdx.x * BN;
    const int wm = (wid & 3) * 32, wn = (wid >> 2) * 64;

    float acc[2][8][4];
#pragma unroll
    for (int i = 0; i < 2; i++)
#pragma unroll
        for (int j = 0; j < 8; j++)
#pragma unroll
            for (int q = 0; q < 4; q++) acc[i][j][q] = 0.f;

    gemm_mainloop(acc, g_ctx1, g_wTH[3], g_wTL[3],
                  m0, n0, smbase, tid, lane, wm, wn);

    const int tr = lane >> 2, tc = (lane & 3) * 2;
#pragma unroll
    for (int i = 0; i < 2; i++) {
#pragma unroll
        for (int hh = 0; hh < 2; hh++) {
            const int m = m0 + wm + i * 16 + tr + hh * 8;
            float* p = outp + (size_t)m * D_ + n0 + wn + tc;
#pragma unroll
            for (int j = 0; j < 8; j++) {
                const int n = n0 + wn + j * 8 + tc;
                float2 o;
                o.x = acc[i][j][hh * 2 + 0] + bias[n];
                o.y = acc[i][j][hh * 2 + 1] + bias[n + 1];
                *(float2*)(p + j * 8) = o;
            }
        }
    }
}

// ==================== mma.sync flash attention (fp16, single-term) ====================
constexpr int KT = 64;
constexpr int KPAD = 72;                          // padded row (halves), 144 B
constexpr int QTILE = 128 * KPAD * 2;             // 18432 B
constexpr int ATILE = KT * KPAD * 2;              // 9216 B
constexpr int ASTAGE = 2 * ATILE;                 // K, V = 18432 B
constexpr int ASMEM = QTILE + 2 * ASTAGE;         // 55296 B

__global__ __launch_bounds__(256, 2) void attn_mma_kernel(const int* __restrict__ mask) {
    extern __shared__ __align__(128) char smem_raw[];
    const uint32_t smbase = smem_to_u32(smem_raw);
    const int tid = threadIdx.x, wid = tid >> 5, lane = tid & 31;
    const int bh = blockIdx.y, b = bh >> 4, h = bh & 15;
    const int q0 = blockIdx.x * 128;

    const size_t hb = (size_t)bh * S_ * DK_;
    const __half* Qg = g_Q1 + hb;
    const __half* Kg = g_K1 + hb;
    const __half* Vg = g_V1 + hb;

    // ---- issue Q tile loads: 1024 x 16B chunks ----
#pragma unroll
    for (int it = 0; it < 4; it++) {
        int flat = tid + it * 256;
        int row = flat >> 3, c8 = flat & 7;
        cp_async16(smbase + row * (KPAD * 2) + c8 * 16,
                   Qg + (size_t)(q0 + row) * DK_ + c8 * 8);
    }
    cp_commit();

    auto issue_stage = [&](int t) {
        const int k0t = t * KT;
        const uint32_t st = smbase + QTILE + (t & 1) * ASTAGE;
#pragma unroll
        for (int it = 0; it < 4; it++) {            // 1024 x 16B chunks (K + V)
            int flat = tid + it * 256;
            int tile = flat >> 9, rem = flat & 511;
            int row = rem >> 3, c8 = rem & 7;
            const __half* src = (tile == 0 ? Kg : Vg) + (size_t)(k0t + row) * DK_ + c8 * 8;
            cp_async16(st + tile * ATILE + row * (KPAD * 2) + c8 * 16, src);
        }
        cp_commit();
    };

    issue_stage(0);

    uint32_t qh[4][4];
    float o[8][4];
#pragma unroll
    for (int i = 0; i < 8; i++)
#pragma unroll
        for (int j = 0; j < 4; j++) o[i][j] = 0.f;
    float m0 = -1e30f, m1 = -1e30f, l0 = 0.f, l1 = 0.f;

    const int tr = lane >> 2, tc2 = (lane & 3) * 2;

#pragma unroll 1
    for (int t = 0; t < S_ / KT; t++) {
        if (t + 1 < S_ / KT) { issue_stage(t + 1); cp_wait<1>(); }
        else                 { cp_wait<0>(); }
        __syncthreads();

        if (t == 0) {
            const int arow = wid * 16 + (lane & 15);
            const int acol = (lane >> 4) * 8;
#pragma unroll
            for (int kt = 0; kt < 4; kt++) {
                uint32_t off = (arow * KPAD + kt * 16 + acol) * 2;
                ldm_x4(qh[kt][0], qh[kt][1], qh[kt][2], qh[kt][3], smbase + off);
            }
        }

        const uint32_t kb = smbase + QTILE + (t & 1) * ASTAGE;

        // ---- QK^T: scores [16 q x 64 k] per warp, single-term ----
        float sc[8][4];
#pragma unroll
        for (int i = 0; i < 8; i++)
#pragma unroll
            for (int j = 0; j < 4; j++) sc[i][j] = 0.f;

#pragma unroll
        for (int kt = 0; kt < 4; kt++) {
            const int brow = ((lane >> 4) & 1) * 8 + (lane & 7);
            const int bcol = kt * 16 + ((lane >> 3) & 1) * 8;
#pragma unroll
            for (int g = 0; g < 4; g++) {
                uint32_t off = ((g * 16 + brow) * KPAD + bcol) * 2;
                uint32_t bv[4];
                ldm_x4(bv[0], bv[1], bv[2], bv[3], kb + off);
                mma_f16(sc[2 * g + 0], qh[kt], bv + 0);
                mma_f16(sc[2 * g + 1], qh[kt], bv + 2);
            }
        }

        // ---- mask + online softmax ----
        const int2* mrow2 = (const int2*)(mask + b * S_ + t * KT);
        float mx0 = -3.4e38f, mx1 = -3.4e38f;
#pragma unroll
        for (int nt = 0; nt < 8; nt++) {
            int2 mv = mrow2[nt * 4 + (lane & 3)];
            if (mv.x == 0) { sc[nt][0] += NEGB; sc[nt][2] += NEGB; }
            if (mv.y == 0) { sc[nt][1] += NEGB; sc[nt][3] += NEGB; }
            mx0 = fmaxf(mx0, fmaxf(sc[nt][0], sc[nt][1]));
            mx1 = fmaxf(mx1, fmaxf(sc[nt][2], sc[nt][3]));
        }
        mx0 = fmaxf(mx0, __shfl_xor_sync(0xffffffffu, mx0, 1));
        mx0 = fmaxf(mx0, __shfl_xor_sync(0xffffffffu, mx0, 2));
        mx1 = fmaxf(mx1, __shfl_xor_sync(0xffffffffu, mx1, 1));
        mx1 = fmaxf(mx1, __shfl_xor_sync(0xffffffffu, mx1, 2));

        float m0n = fmaxf(m0, mx0), m1n = fmaxf(m1, mx1);
        float c0 = ex2(m0 - m0n), c1 = ex2(m1 - m1n);
        m0 = m0n; m1 = m1n;

        float sum0 = 0.f, sum1 = 0.f;
#pragma unroll
        for (int nt = 0; nt < 8; nt++) {
            sc[nt][0] = ex2(sc[nt][0] - m0n);
            sc[nt][1] = ex2(sc[nt][1] - m0n);
            sc[nt][2] = ex2(sc[nt][2] - m1n);
            sc[nt][3] = ex2(sc[nt][3] - m1n);
            sum0 += sc[nt][0] + sc[nt][1];
            sum1 += sc[nt][2] + sc[nt][3];
        }
        sum0 += __shfl_xor_sync(0xffffffffu, sum0, 1);
        sum0 += __shfl_xor_sync(0xffffffffu, sum0, 2);
        sum1 += __shfl_xor_sync(0xffffffffu, sum1, 1);
        sum1 += __shfl_xor_sync(0xffffffffu, sum1, 2);
        l0 = l0 * c0 + sum0;
        l1 = l1 * c1 + sum1;

        // rescale O
#pragma unroll
        for (int i = 0; i < 8; i++) {
            o[i][0] *= c0; o[i][1] *= c0;
            o[i][2] *= c1; o[i][3] *= c1;
        }

        // ---- P @ V: single-term fp16 P x V (ldmatrix.trans) ----
#pragma unroll
        for (int kk = 0; kk < 4; kk++) {
            uint32_t ph[4];
            ph[0] = pack2(sc[2 * kk + 0][0], sc[2 * kk + 0][1]);
            ph[1] = pack2(sc[2 * kk + 0][2], sc[2 * kk + 0][3]);
            ph[2] = pack2(sc[2 * kk + 1][0], sc[2 * kk + 1][1]);
            ph[3] = pack2(sc[2 * kk + 1][2], sc[2 * kk + 1][3]);

            const int krow = kk * 16 + ((lane >> 3) & 1) * 8 + (lane & 7);
            const int dcol = ((lane >> 4) & 1) * 8;
#pragma unroll
            for (int g = 0; g < 4; g++) {
                uint32_t off = (krow * KPAD + g * 16 + dcol) * 2;
                uint32_t bv[4];
                ldm_x4_t(bv[0], bv[1], bv[2], bv[3], kb + ATILE + off);
                mma_f16(o[2 * g + 0], ph, bv + 0);
                mma_f16(o[2 * g + 1], ph, bv + 2);
            }
        }
        __syncthreads();
    }

    // ---- epilogue: O / l -> single fp16 ctx ----
    const float inv0 = 1.f / l0, inv1 = 1.f / l1;
    const int r0 = q0 + wid * 16 + tr;
    const size_t base0 = ((size_t)(b * S_ + r0)) * D_ + h * DK_;
    const size_t base1 = ((size_t)(b * S_ + r0 + 8)) * D_ + h * DK_;
#pragma unroll
    for (int nt = 0; nt < 8; nt++) {
        const int d0 = nt * 8 + tc2;
        *(uint32_t*)&g_ctx1[base0 + d0] = pack2(o[nt][0] * inv0, o[nt][1] * inv0);
        *(uint32_t*)&g_ctx1[base1 + d0] = pack2(o[nt][2] * inv1, o[nt][3] * inv1);
    }
}

// ==================== launch ====================
extern "C" void kernel_launch(void* const* d_in, const int* in_sizes, int n_in,
                              void* d_out, int out_size) {
    const float* query = (const float*)d_in[0];
    const float* key   = (const float*)d_in[1];
    const float* value = (const float*)d_in[2];
    const int*   mask  = (const int*)d_in[3];
    const float* Wq = (const float*)d_in[4];
    const float* bq = (const float*)d_in[5];
    const float* Wk = (const float*)d_in[6];
    const float* bk = (const float*)d_in[7];
    const float* Wv = (const float*)d_in[8];
    const float* bv = (const float*)d_in[9];
    const float* Wo = (const float*)d_in[10];
    const float* bo = (const float*)d_in[11];
    float* out = (float*)d_out;

    cudaFuncSetAttribute(gemm_qkv_kernel, cudaFuncAttributeMaxDynamicSharedMemorySize, GSMEM);
    cudaFuncSetAttribute(gemm_out_kernel, cudaFuncAttributeMaxDynamicSharedMemorySize, GSMEM);
    cudaFuncSetAttribute(attn_mma_kernel, cudaFuncAttributeMaxDynamicSharedMemorySize, ASMEM);

    // weight transpose + fp16 split (one launch, z = 4)
    dim3 wtg(D_ / 32, D_ / 32, 4), wtb(32, 8);
    conv_wT_kernel<<<wtg, wtb>>>(Wq, Wk, Wv, Wo);

    // activation fp16 convert (one launch, z = 3)
    dim3 cg((M_ * D_ / 4) / 256, 1, 3);
    conv_act_kernel<<<cg, 256>>>(query, key, value);

    // QKV projections merged into one launch (z = 3)
    dim3 gq(D_ / BN, M_ / BM, 3);            // (8, 32, 3) = 768 CTAs
    gemm_qkv_kernel<<<gq, 256, GSMEM>>>(bq, bk, bv);

    // flash attention on tensor cores
    dim3 ga(S_ / 128, B_ * H_);              // (16, 32)
    attn_mma_kernel<<<ga, 256, ASMEM>>>(mask);

    // output projection
    dim3 gg(D_ / BN, M_ / BM);               // (8, 32)
    gemm_out_kernel<<<gg, 256, GSMEM>>>(bo, out);
}